// round 12
// baseline (speedup 1.0000x reference)
#include <cuda_runtime.h>
#include <cuda_bf16.h>
#include <math.h>
#include <stdint.h>

#define BB 32
#define HID 2048
#define INNER 4096
#define NH 8
#define HEAD 512
#define K3 12288
#define CAP 30.0f
#define EPS 1e-6f
#define GN_EPS 1e-5f
#define KSCALE 0.044194173824159216f   // 1/sqrt(512)

// ---------------- scratch (device globals; no allocs allowed) ----------------
__device__ float g_xn   [BB * HID];
__device__ float g_xg   [BB * INNER];
__device__ float g_xmc  [BB * INNER];
__device__ float g_qkv  [BB * K3];
__device__ float g_h    [BB * INNER];
__device__ float g_part [16 * BB * K3];            // split-K partials
__device__ float g_numer[BB * NH * 4 * HEAD];      // cell numer partials
__device__ float g_ig   [BB * NH];
__device__ float g_fg   [BB * NH];

// ---------------- output layout ----------------
#define Y_OFF    0
#define CONV_OFF 65536
#define CELL_OFF 458752
#define NORM_OFF 67567616
#define MAX_OFF  67698688

// ---------------- mma.sync helpers (sm_80 baseline PTX -> HMMA) -------------
__device__ __forceinline__ unsigned pack2(float c0, float c1) {
    unsigned r;
    asm("cvt.rn.satfinite.bf16x2.f32 %0, %1, %2;" : "=r"(r) : "f"(c1), "f"(c0));
    return r;
}

__device__ __forceinline__ void ldm4(unsigned& r0, unsigned& r1,
                                     unsigned& r2, unsigned& r3, unsigned addr) {
    asm volatile("ldmatrix.sync.aligned.m8n8.x4.shared.b16 {%0,%1,%2,%3}, [%4];"
                 : "=r"(r0), "=r"(r1), "=r"(r2), "=r"(r3) : "r"(addr));
}

__device__ __forceinline__ void mma16816(float* d, const unsigned* a,
                                         unsigned b0, unsigned b1) {
    asm volatile(
        "mma.sync.aligned.m16n8k16.row.col.f32.bf16.bf16.f32 "
        "{%0,%1,%2,%3}, {%4,%5,%6,%7}, {%8,%9}, {%0,%1,%2,%3};"
        : "+f"(d[0]), "+f"(d[1]), "+f"(d[2]), "+f"(d[3])
        : "r"(a[0]), "r"(a[1]), "r"(a[2]), "r"(a[3]), "r"(b0), "r"(b1));
}

__device__ __forceinline__ void cvt_hilo(float4 v, uint2& hi, uint2& lo) {
    unsigned hi01 = pack2(v.x, v.y);
    unsigned hi23 = pack2(v.z, v.w);
    float h0 = __uint_as_float(hi01 << 16);
    float h1 = __uint_as_float(hi01 & 0xFFFF0000u);
    float h2 = __uint_as_float(hi23 << 16);
    float h3 = __uint_as_float(hi23 & 0xFFFF0000u);
    hi = make_uint2(hi01, hi23);
    lo = make_uint2(pack2(v.x - h0, v.y - h1), pack2(v.z - h2, v.w - h3));
}

// ============================================================================
// MMA GEMM v4: C[32,N] = A[32,K] @ W[N,K]^T, bf16 hi/lo x3, split-K partials.
// 256 thr, BN=128, BK=32. Depth-2 REGISTER prefetch (no fp32 smem stage):
//   convert regs[buf] -> bf16 smem -> sync -> LDG ch+2 -> regs[buf] -> compute.
// Warp (of 8): 16m x 32n tile. Partial layout: [splitIdx][32][nrows].
// ============================================================================
#define SW 40   // bf16 smem row stride (80B) - ldmatrix conflict-free

__global__ __launch_bounds__(256) void mma_gemm(
    const float* __restrict__ A,
    const float* __restrict__ W1, float* __restrict__ P1, int n1,
    const float* __restrict__ W2, float* __restrict__ P2, int n2,
    int nb1, int Kt, int kLen)
{
    __shared__ __align__(16) __nv_bfloat16 sWhi[128 * SW];
    __shared__ __align__(16) __nv_bfloat16 sWlo[128 * SW];
    __shared__ __align__(16) __nv_bfloat16 sAhi[32 * SW];
    __shared__ __align__(16) __nv_bfloat16 sAlo[32 * SW];

    const int t = threadIdx.x;
    const int bx = blockIdx.x;
    const bool fw = bx < nb1;
    const float* W = fw ? W1 : W2;
    float* P = fw ? P1 : P2;
    const int nrows = fw ? n1 : n2;
    const int n0 = (fw ? bx : bx - nb1) * 128;
    const int kBeg = blockIdx.y * kLen;
    const int NCH = kLen >> 5;

    const int wid = t >> 5, l = t & 31;
    const int wm = (wid & 1) * 16;
    const int wn = (wid >> 1) * 32;

    const unsigned swhi = (unsigned)__cvta_generic_to_shared(sWhi);
    const unsigned swlo = (unsigned)__cvta_generic_to_shared(sWlo);
    const unsigned sahi = (unsigned)__cvta_generic_to_shared(sAhi);
    const unsigned salo = (unsigned)__cvta_generic_to_shared(sAlo);

    const int lr = t >> 3;        // 0..31  (row within 32-row group)
    const int lc = t & 7;         // float4 column
    const float* wsrc = W + (size_t)(n0 + lr) * Kt + kBeg + lc * 4;
    const float* asrc = A + (size_t)lr * Kt + kBeg + lc * 4;
    const int sbi = lr * SW + lc * 4;

    float acc[4][4];
    #pragma unroll
    for (int i = 0; i < 4; i++)
        #pragma unroll
        for (int j = 0; j < 4; j++) acc[i][j] = 0.f;

    // depth-2 register prefetch buffers
    float4 wpre[2][4], apre[2];
    #pragma unroll
    for (int p = 0; p < 4; p++)
        wpre[0][p] = *(const float4*)(wsrc + (size_t)(p * 32) * Kt);
    apre[0] = *(const float4*)asrc;
    if (NCH > 1) {
        #pragma unroll
        for (int p = 0; p < 4; p++)
            wpre[1][p] = *(const float4*)(wsrc + (size_t)(p * 32) * Kt + 32);
        apre[1] = *(const float4*)(asrc + 32);
    }

    for (int ch = 0; ch < NCH; ch++) {
        const int buf = ch & 1;
        if (ch) __syncthreads();   // prior compute finished reading bf16 smem

        // convert regs[buf] -> bf16 hi/lo smem
        #pragma unroll
        for (int p = 0; p < 4; p++) {
            uint2 hi, lo; cvt_hilo(wpre[buf][p], hi, lo);
            *(uint2*)&sWhi[p * 32 * SW + sbi] = hi;
            *(uint2*)&sWlo[p * 32 * SW + sbi] = lo;
        }
        {
            uint2 hi, lo; cvt_hilo(apre[buf], hi, lo);
            *(uint2*)&sAhi[sbi] = hi;
            *(uint2*)&sAlo[sbi] = lo;
        }
        __syncthreads();

        // issue chunk ch+2 loads into regs[buf] (consumed 2 iterations later)
        if (ch + 2 < NCH) {
            #pragma unroll
            for (int p = 0; p < 4; p++)
                wpre[buf][p] = *(const float4*)(wsrc + (size_t)(p * 32) * Kt + (ch + 2) * 32);
            apre[buf] = *(const float4*)(asrc + (ch + 2) * 32);
        }

        // compute: 2 k16 steps
        #pragma unroll
        for (int s = 0; s < 2; s++) {
            const int ks = s * 16;
            unsigned arow = wm + ((l >> 3) & 1) * 8 + (l & 7);
            unsigned acol = ks + ((l >> 4) & 1) * 8;
            unsigned aoff = (arow * SW + acol) * 2;
            unsigned ahi[4], alo[4];
            ldm4(ahi[0], ahi[1], ahi[2], ahi[3], sahi + aoff);
            ldm4(alo[0], alo[1], alo[2], alo[3], salo + aoff);
            unsigned brow = wn + ((l >> 4) & 1) * 8 + (l & 7);
            unsigned bcol = ks + ((l >> 3) & 1) * 8;
            unsigned boff0 = (brow * SW + bcol) * 2;
            unsigned boff1 = ((brow + 16) * SW + bcol) * 2;
            unsigned bhi[8], blo[8];
            ldm4(bhi[0], bhi[1], bhi[2], bhi[3], swhi + boff0);
            ldm4(bhi[4], bhi[5], bhi[6], bhi[7], swhi + boff1);
            ldm4(blo[0], blo[1], blo[2], blo[3], swlo + boff0);
            ldm4(blo[4], blo[5], blo[6], blo[7], swlo + boff1);
            #pragma unroll
            for (int tt = 0; tt < 4; tt++) {
                mma16816(acc[tt], ahi, bhi[tt*2], bhi[tt*2+1]);
                mma16816(acc[tt], ahi, blo[tt*2], blo[tt*2+1]);
                mma16816(acc[tt], alo, bhi[tt*2], bhi[tt*2+1]);
            }
        }
    }

    // ---- epilogue: partials [split][b][n] ----
    const int r0 = wm + (l >> 2);
    const int cb = n0 + wn + 2 * (l & 3);
    float* p0 = P + ((size_t)blockIdx.y * 32 + r0) * nrows;
    float* p1 = p0 + (size_t)8 * nrows;
    #pragma unroll
    for (int tt = 0; tt < 4; tt++) {
        *(float2*)(p0 + cb + tt * 8) = make_float2(acc[tt][0], acc[tt][1]);
        *(float2*)(p1 + cb + tt * 8) = make_float2(acc[tt][2], acc[tt][3]);
    }
}

// ============================================================================
// RMSNorm
// ============================================================================
__global__ void rmsnorm_kernel(const float* __restrict__ x,
                               const float* __restrict__ rms_w)
{
    __shared__ float red[256];
    int b = blockIdx.x;
    int tid = threadIdx.x;
    const float* xr = x + b * HID;
    float s = 0.f;
    for (int i = tid; i < HID; i += 256) { float v = xr[i]; s += v * v; }
    red[tid] = s; __syncthreads();
    for (int st = 128; st > 0; st >>= 1) {
        if (tid < st) red[tid] += red[tid + st];
        __syncthreads();
    }
    float rstd = rsqrtf(red[0] / (float)HID + EPS);
    float* o = g_xn + b * HID;
    for (int i = tid; i < HID; i += 256) o[i] = xr[i] * rstd * rms_w[i];
}

// ============================================================================
// Split-K reduce: C = sum_s part[s] (+ addv)
// ============================================================================
template<int S>
__global__ void reduce_split_t(const float* __restrict__ part, int elems,
                               const float* __restrict__ addv,
                               float* __restrict__ C)
{
    int i = blockIdx.x * blockDim.x + threadIdx.x;
    const float4* p = (const float4*)part;
    int q = elems >> 2;
    float4 s = p[i];
    #pragma unroll
    for (int j = 1; j < S; j++) {
        float4 t = p[i + (size_t)j * q];
        s.x += t.x; s.y += t.y; s.z += t.z; s.w += t.w;
    }
    if (addv) {
        float4 a = ((const float4*)addv)[i];
        s.x += a.x; s.y += a.y; s.z += a.z; s.w += a.w;
    }
    ((float4*)C)[i] = s;
}

// ============================================================================
// Conv + fused xm split-4 reduce + silu + new_conv_state
// ============================================================================
__global__ void conv_kernel(const float* __restrict__ conv_state,
                            const float* __restrict__ conv_w,
                            const float* __restrict__ conv_b,
                            const float* __restrict__ xm_part,
                            float* __restrict__ out)
{
    int idx = blockIdx.x * blockDim.x + threadIdx.x;
    if (idx >= BB * INNER) return;
    int c = idx & (INNER - 1);
    float xm = 0.f;
    #pragma unroll
    for (int s = 0; s < 4; s++) xm += xm_part[(size_t)s * BB * INNER + idx];
    const float* cs = conv_state + (size_t)idx * 3;
    float s0 = cs[0], s1 = cs[1], s2 = cs[2];
    const float* w = conv_w + c * 4;
    float xc = s0*w[0] + s1*w[1] + s2*w[2] + xm*w[3] + conv_b[c];
    float* nc = out + CONV_OFF + (size_t)idx * 3;
    nc[0] = s1; nc[1] = s2; nc[2] = xm;
    g_xmc[idx] = xc / (1.f + expf(-xc));
}

// ============================================================================
// Gates
// ============================================================================
__global__ __launch_bounds__(256) void gate_kernel(
    const float* __restrict__ Wi, const float* __restrict__ bi,
    const float* __restrict__ Wf, const float* __restrict__ bf,
    const float* __restrict__ max_state,
    float* __restrict__ out)
{
    __shared__ float ri[256], rf[256];
    int bh = blockIdx.x;
    int h = bh & (NH - 1);
    int b = bh >> 3;
    int tid = threadIdx.x;
    const float4* q4  = (const float4*)(g_qkv + (size_t)b * K3);
    const float4* wi4 = (const float4*)(Wi + (size_t)h * K3);
    const float4* wf4 = (const float4*)(Wf + (size_t)h * K3);
    float si = 0.f, sf = 0.f;
    #pragma unroll
    for (int r = 0; r < K3/4/256; r++) {
        int j = tid + r * 256;
        float4 q = q4[j], a = wi4[j], f = wf4[j];
        si += q.x*a.x + q.y*a.y + q.z*a.z + q.w*a.w;
        sf += q.x*f.x + q.y*f.y + q.z*f.z + q.w*f.w;
    }
    ri[tid] = si; rf[tid] = sf; __syncthreads();
    for (int st = 128; st > 0; st >>= 1) {
        if (tid < st) { ri[tid] += ri[tid+st]; rf[tid] += rf[tid+st]; }
        __syncthreads();
    }
    if (tid == 0) {
        float ig = CAP * tanhf((ri[0] + bi[h]) / CAP);
        float fg = CAP * tanhf((rf[0] + bf[h]) / CAP);
        float lf = (fg >= 0.f) ? -log1pf(expf(-fg)) : (fg - log1pf(expf(fg)));
        float m_old = max_state[bh];
        float m_new = fmaxf(ig, m_old + lf);
        g_ig[bh] = expf(ig - m_new);
        g_fg[bh] = expf(lf + m_old - m_new);
        out[MAX_OFF + bh] = m_new;
    }
}

// ============================================================================
// Cell stream: grid = 4 chunks x 256 bh; 256 threads.
// ============================================================================
__global__ __launch_bounds__(256) void cell_stream(
    const float* __restrict__ cell_state,
    float* __restrict__ out)
{
    __shared__ float qsm[128], ksm[128];
    __shared__ float part[2][HEAD];

    const int bid = blockIdx.x;
    const int bh = bid >> 2;
    const int ch = bid & 3;
    const int h = bh & (NH - 1);
    const int b = bh >> 3;
    const int tid = threadIdx.x;

    const float* qrow = g_qkv + (size_t)b * K3 + h * HEAD;
    const float* krow = qrow + INNER;
    const float* vrow = qrow + 2 * INNER;
    const int d0 = ch * 128;

    if (tid < 128) {
        qsm[tid] = qrow[d0 + tid];
        ksm[tid] = krow[d0 + tid] * KSCALE;
    }
    __syncthreads();

    const float ig = g_ig[bh];
    const float fg = g_fg[bh];

    const int ct = tid & 127;
    const int rg = tid >> 7;
    const int e0 = ct * 4;
    float4 v = *(const float4*)(vrow + e0);
    float4 iv = make_float4(ig*v.x, ig*v.y, ig*v.z, ig*v.w);

    const float* cin  = cell_state + (size_t)bh * HEAD * HEAD;
    float*       cout = out + CELL_OFF + (size_t)bh * HEAD * HEAD;

    float4 nacc = make_float4(0.f, 0.f, 0.f, 0.f);
    #pragma unroll 8
    for (int dd = rg; dd < 128; dd += 2) {
        int d = d0 + dd;
        float4 cv = *(const float4*)(cin + (size_t)d * HEAD + e0);
        float kd = ksm[dd];
        float4 c;
        c.x = fmaf(fg, cv.x, kd * iv.x);
        c.y = fmaf(fg, cv.y, kd * iv.y);
        c.z = fmaf(fg, cv.z, kd * iv.z);
        c.w = fmaf(fg, cv.w, kd * iv.w);
        *(float4*)(cout + (size_t)d * HEAD + e0) = c;
        float qd = qsm[dd];
        nacc.x = fmaf(qd, c.x, nacc.x);
        nacc.y = fmaf(qd, c.y, nacc.y);
        nacc.z = fmaf(qd, c.z, nacc.z);
        nacc.w = fmaf(qd, c.w, nacc.w);
    }
    *(float4*)&part[rg][e0] = nacc;
    __syncthreads();
    if (tid < 128) {
        float4 p0 = *(const float4*)&part[0][e0];
        float4 p1 = *(const float4*)&part[1][e0];
        float4 s = make_float4(p0.x+p1.x, p0.y+p1.y, p0.z+p1.z, p0.w+p1.w);
        *(float4*)(g_numer + (size_t)bid * HEAD + e0) = s;
    }
}

// ============================================================================
// Cell epilogue: norm_new + qn + denom + GroupNorm + gating -> h
// (x_gate split-4 reduce fused)
// ============================================================================
__global__ __launch_bounds__(512) void cell_epi(
    const float* __restrict__ norm_state,
    const float* __restrict__ gn_w, const float* __restrict__ gn_b,
    const float* __restrict__ skip_w,
    const float* __restrict__ xg_part,
    float* __restrict__ out)
{
    __shared__ float red[512];
    const int bh = blockIdx.x;
    const int h = bh & (NH - 1);
    const int b = bh >> 3;
    const int tid = threadIdx.x;

    const float* qrow = g_qkv + (size_t)b * K3 + h * HEAD;
    const float* krow = qrow + INNER;
    float q = qrow[tid];
    float k = krow[tid] * KSCALE;

    const float ig = g_ig[bh];
    const float fg = g_fg[bh];
    const float m_new = out[MAX_OFF + bh];

    float num = g_numer[(size_t)(bh*4+0) * HEAD + tid]
              + g_numer[(size_t)(bh*4+1) * HEAD + tid]
              + g_numer[(size_t)(bh*4+2) * HEAD + tid]
              + g_numer[(size_t)(bh*4+3) * HEAD + tid];

    float nn = fmaf(fg, norm_state[(size_t)bh * HEAD + tid], ig * k);
    out[NORM_OFF + (size_t)bh * HEAD + tid] = nn;

    red[tid] = q * nn; __syncthreads();
    for (int st = 256; st > 0; st >>= 1) {
        if (tid < st) red[tid] += red[tid+st];
        __syncthreads();
    }
    float qn = red[0]; __syncthreads();
    float denom = fmaxf(fabsf(qn), expf(-m_new)) + EPS;
    float o = num / denom;

    red[tid] = o; __syncthreads();
    for (int st = 256; st > 0; st >>= 1) {
        if (tid < st) red[tid] += red[tid+st];
        __syncthreads();
    }
    float mu = red[0] / (float)HEAD; __syncthreads();
    float dv = o - mu;
    red[tid] = dv * dv; __syncthreads();
    for (int st = 256; st > 0; st >>= 1) {
        if (tid < st) red[tid] += red[tid+st];
        __syncthreads();
    }
    float rstd = rsqrtf(red[0] / (float)HEAD + GN_EPS);

    int c = h * HEAD + tid;
    size_t gidx = (size_t)b * INNER + c;
    float xg = 0.f;
    #pragma unroll
    for (int s = 0; s < 4; s++) xg += xg_part[(size_t)s * BB * INNER + gidx];
    float og = fmaf(dv * rstd, gn_w[c], gn_b[c]);
    float sg = xg / (1.f + expf(-xg));
    g_h[gidx] = (og + skip_w[c] * g_xmc[gidx]) * sg;
}

// ============================================================================
extern "C" void kernel_launch(void* const* d_in, const int* in_sizes, int n_in,
                              void* d_out, int out_size)
{
    const float* x          = (const float*)d_in[0];
    const float* conv_state = (const float*)d_in[1];
    const float* cell_state = (const float*)d_in[2];
    const float* norm_state = (const float*)d_in[3];
    const float* max_state  = (const float*)d_in[4];
    const float* rms_w      = (const float*)d_in[5];
    const float* Wx         = (const float*)d_in[6];
    const float* Wg         = (const float*)d_in[7];
    const float* Wqkv       = (const float*)d_in[8];
    const float* conv_w     = (const float*)d_in[9];
    const float* conv_b     = (const float*)d_in[10];
    const float* Wi         = (const float*)d_in[11];
    const float* bi         = (const float*)d_in[12];
    const float* Wf         = (const float*)d_in[13];
    const float* bf         = (const float*)d_in[14];
    const float* gn_w       = (const float*)d_in[15];
    const float* gn_b       = (const float*)d_in[16];
    const float* Wdown      = (const float*)d_in[17];
    const float* skip_w     = (const float*)d_in[18];
    float* out = (float*)d_out;

    float* pxn;   cudaGetSymbolAddress((void**)&pxn,   g_xn);
    float* pxmc;  cudaGetSymbolAddress((void**)&pxmc,  g_xmc);
    float* pqkv;  cudaGetSymbolAddress((void**)&pqkv,  g_qkv);
    float* ph;    cudaGetSymbolAddress((void**)&ph,    g_h);
    float* ppart; cudaGetSymbolAddress((void**)&ppart, g_part);

    // Wg partials: beyond QKV's 4-split region [0, 4*BB*K3)
    float* pp2 = ppart + (size_t)4 * BB * K3;

    // 1) rmsnorm
    rmsnorm_kernel<<<BB, 256>>>(x, rms_w);

    // 2) x_mlstm & x_gate tensor-core GEMM, split-K 4: grid (32+32, 4) = 256
    mma_gemm<<<dim3(64, 4), 256>>>(pxn, Wx, ppart, INNER,
                                   Wg, pp2, INNER, 32, HID, HID/4);

    // 3) conv (fused xm split-4 reduce) + silu + new_conv_state
    conv_kernel<<<(BB*INNER)/256, 256>>>(conv_state, conv_w, conv_b, ppart, out);

    // 4) qkv = xmc @ Wqkv^T, split-K 4: grid (96, 4) = 384
    mma_gemm<<<dim3(96, 4), 256>>>(pxmc, Wqkv, ppart, K3,
                                   Wqkv, ppart, K3, 96, INNER, INNER/4);
    reduce_split_t<4><<<(BB*K3/4)/256, 256>>>(ppart, BB*K3, nullptr, pqkv);

    // 5) gates
    gate_kernel<<<BB*NH, 256>>>(Wi, bi, Wf, bf, max_state, out);

    // 6) cell stream: 1024 blocks
    cell_stream<<<BB*NH*4, 256>>>(cell_state, out);

    // 7) cell epilogue (fused xg reduce) -> h
    cell_epi<<<BB*NH, 512>>>(norm_state, gn_w, gn_b, skip_w, pp2, out);

    // 8) y = h @ Wdown^T + x, split-K 8: grid (16, 8) = 128
    mma_gemm<<<dim3(16, 8), 256>>>(ph, Wdown, ppart, HID,
                                   Wdown, ppart, HID, 16, INNER, INNER/8);
    reduce_split_t<8><<<(BB*HID/4)/256, 256>>>(ppart, BB*HID, x, out + Y_OFF);
}

// round 13
// speedup vs baseline: 1.2348x; 1.2348x over previous
#include <cuda_runtime.h>
#include <cuda_bf16.h>
#include <math.h>
#include <stdint.h>

#define BB 32
#define HID 2048
#define INNER 4096
#define NH 8
#define HEAD 512
#define K3 12288
#define CAP 30.0f
#define EPS 1e-6f
#define GN_EPS 1e-5f
#define KSCALE 0.044194173824159216f   // 1/sqrt(512)

// ---------------- scratch (device globals; no allocs allowed) ----------------
__device__ float g_xn   [BB * HID];
__device__ float g_xg   [BB * INNER];
__device__ float g_xmc  [BB * INNER];
__device__ float g_qkv  [BB * K3];
__device__ float g_h    [BB * INNER];
__device__ float g_part [16 * BB * K3];            // split-K partials
__device__ float g_numer[BB * NH * 4 * HEAD];      // cell numer partials
__device__ float g_ig   [BB * NH];
__device__ float g_fg   [BB * NH];

// ---------------- output layout ----------------
#define Y_OFF    0
#define CONV_OFF 65536
#define CELL_OFF 458752
#define NORM_OFF 67567616
#define MAX_OFF  67698688

// ---------------- mma.sync helpers (sm_80 baseline PTX -> HMMA) -------------
__device__ __forceinline__ unsigned pack2(float c0, float c1) {
    unsigned r;
    asm("cvt.rn.satfinite.bf16x2.f32 %0, %1, %2;" : "=r"(r) : "f"(c1), "f"(c0));
    return r;
}

__device__ __forceinline__ void ldm4(unsigned& r0, unsigned& r1,
                                     unsigned& r2, unsigned& r3, unsigned addr) {
    asm volatile("ldmatrix.sync.aligned.m8n8.x4.shared.b16 {%0,%1,%2,%3}, [%4];"
                 : "=r"(r0), "=r"(r1), "=r"(r2), "=r"(r3) : "r"(addr));
}

__device__ __forceinline__ void mma16816(float* d, const unsigned* a,
                                         unsigned b0, unsigned b1) {
    asm volatile(
        "mma.sync.aligned.m16n8k16.row.col.f32.bf16.bf16.f32 "
        "{%0,%1,%2,%3}, {%4,%5,%6,%7}, {%8,%9}, {%0,%1,%2,%3};"
        : "+f"(d[0]), "+f"(d[1]), "+f"(d[2]), "+f"(d[3])
        : "r"(a[0]), "r"(a[1]), "r"(a[2]), "r"(a[3]), "r"(b0), "r"(b1));
}

__device__ __forceinline__ void cvt_hilo(float4 v, uint2& hi, uint2& lo) {
    unsigned hi01 = pack2(v.x, v.y);
    unsigned hi23 = pack2(v.z, v.w);
    float h0 = __uint_as_float(hi01 << 16);
    float h1 = __uint_as_float(hi01 & 0xFFFF0000u);
    float h2 = __uint_as_float(hi23 << 16);
    float h3 = __uint_as_float(hi23 & 0xFFFF0000u);
    hi = make_uint2(hi01, hi23);
    lo = make_uint2(pack2(v.x - h0, v.y - h1), pack2(v.z - h2, v.w - h3));
}

__device__ __forceinline__ void cp16(void* smem_p, const void* g) {
    unsigned s = (unsigned)__cvta_generic_to_shared(smem_p);
    asm volatile("cp.async.cg.shared.global [%0], [%1], 16;\n" :: "r"(s), "l"(g));
}

// ============================================================================
// MMA GEMM v5: C[32,N] = A[32,K] @ W[N,K]^T, bf16 hi/lo x3, split-K partials.
// 256 thr, BN=128, BK=32.
//   W: cp.async 2-deep fp32 smem staging (bypasses RF; R11 proven).
//   A: depth-2 REGISTER prefetch (1 float4/thread; fits register budget).
// Warp (of 8): 16m x 32n tile. Partial layout: [splitIdx][32][nrows].
// ============================================================================
#define SW 40   // bf16 smem row stride (80B) - ldmatrix conflict-free
// dynamic smem offsets (bytes)
#define O_WST 0               // fp32 W stage: 2 * 128*32*4 = 32768
#define O_WHI 32768           // 128*SW*2 = 10240
#define O_WLO 43008
#define O_AHI 53248           // 32*SW*2 = 2560
#define O_ALO 55808
#define SMEM_MMA 58368

__global__ __launch_bounds__(256) void mma_gemm(
    const float* __restrict__ A,
    const float* __restrict__ W1, float* __restrict__ P1, int n1,
    const float* __restrict__ W2, float* __restrict__ P2, int n2,
    int nb1, int Kt, int kLen)
{
    extern __shared__ __align__(16) char smem[];
    float* stW = (float*)(smem + O_WST);
    __nv_bfloat16* sWhi = (__nv_bfloat16*)(smem + O_WHI);
    __nv_bfloat16* sWlo = (__nv_bfloat16*)(smem + O_WLO);
    __nv_bfloat16* sAhi = (__nv_bfloat16*)(smem + O_AHI);
    __nv_bfloat16* sAlo = (__nv_bfloat16*)(smem + O_ALO);
    const unsigned sbase = (unsigned)__cvta_generic_to_shared(smem);
    const unsigned swhi = sbase + O_WHI;
    const unsigned swlo = sbase + O_WLO;
    const unsigned sahi = sbase + O_AHI;
    const unsigned salo = sbase + O_ALO;

    const int t = threadIdx.x;
    const int bx = blockIdx.x;
    const bool fw = bx < nb1;
    const float* W = fw ? W1 : W2;
    float* P = fw ? P1 : P2;
    const int nrows = fw ? n1 : n2;
    const int n0 = (fw ? bx : bx - nb1) * 128;
    const int kBeg = blockIdx.y * kLen;
    const int NCH = kLen >> 5;

    const int wid = t >> 5, l = t & 31;
    const int wm = (wid & 1) * 16;
    const int wn = (wid >> 1) * 32;

    const int lr = t >> 3;        // 0..31
    const int lc = t & 7;         // float4 col
    const float* wsrc = W + (size_t)(n0 + lr) * Kt + kBeg + lc * 4;
    const float* asrc = A + (size_t)lr * Kt + kBeg + lc * 4;
    const int wsl = lr * 32 + lc * 4;   // stage slot (per 32-row group)
    const int sbi = lr * SW + lc * 4;   // bf16 smem slot

    float acc[4][4];
    #pragma unroll
    for (int i = 0; i < 4; i++)
        #pragma unroll
        for (int j = 0; j < 4; j++) acc[i][j] = 0.f;

    // prologue: W stage chunks 0,1 via cp.async; A chunks 0,1 in registers
    float4 apre[2];
    {
        #pragma unroll
        for (int p = 0; p < 4; p++)
            cp16(&stW[p * 1024 + wsl], wsrc + (size_t)(p * 32) * Kt);
        asm volatile("cp.async.commit_group;\n");
        #pragma unroll
        for (int p = 0; p < 4; p++)
            cp16(&stW[4096 + p * 1024 + wsl], wsrc + (size_t)(p * 32) * Kt + 32);
        asm volatile("cp.async.commit_group;\n");
        apre[0] = *(const float4*)asrc;
        apre[1] = *(const float4*)(asrc + 32);
    }

    for (int ch = 0; ch < NCH; ch++) {
        const int st = ch & 1;
        if (ch + 1 < NCH) asm volatile("cp.async.wait_group 1;\n");
        else              asm volatile("cp.async.wait_group 0;\n");
        __syncthreads();   // stage ready + prev compute done reading bf16

        // convert fp32 W stage -> bf16 hi/lo smem
        #pragma unroll
        for (int p = 0; p < 4; p++) {
            float4 v = *(const float4*)&stW[st * 4096 + p * 1024 + wsl];
            uint2 hi, lo; cvt_hilo(v, hi, lo);
            int bi = (lr + 32 * p) * SW + lc * 4;
            *(uint2*)&sWhi[bi] = hi;
            *(uint2*)&sWlo[bi] = lo;
        }
        // convert A registers -> bf16 hi/lo smem
        {
            uint2 hi, lo; cvt_hilo(apre[st], hi, lo);
            *(uint2*)&sAhi[sbi] = hi;
            *(uint2*)&sAlo[sbi] = lo;
        }
        __syncthreads();   // bf16 visible; stage reads complete

        // refill stage st with W chunk ch+2; A chunk ch+2 into apre[st]
        if (ch + 2 < NCH) {
            #pragma unroll
            for (int p = 0; p < 4; p++)
                cp16(&stW[st * 4096 + p * 1024 + wsl],
                     wsrc + (size_t)(p * 32) * Kt + (ch + 2) * 32);
            asm volatile("cp.async.commit_group;\n");
            apre[st] = *(const float4*)(asrc + (ch + 2) * 32);
        }

        // compute: 2 k16 steps
        #pragma unroll
        for (int s = 0; s < 2; s++) {
            const int ks = s * 16;
            unsigned arow = wm + ((l >> 3) & 1) * 8 + (l & 7);
            unsigned acol = ks + ((l >> 4) & 1) * 8;
            unsigned aoff = (arow * SW + acol) * 2;
            unsigned ahi[4], alo[4];
            ldm4(ahi[0], ahi[1], ahi[2], ahi[3], sahi + aoff);
            ldm4(alo[0], alo[1], alo[2], alo[3], salo + aoff);
            unsigned brow = wn + ((l >> 4) & 1) * 8 + (l & 7);
            unsigned bcol = ks + ((l >> 3) & 1) * 8;
            unsigned boff0 = (brow * SW + bcol) * 2;
            unsigned boff1 = ((brow + 16) * SW + bcol) * 2;
            unsigned bhi[8], blo[8];
            ldm4(bhi[0], bhi[1], bhi[2], bhi[3], swhi + boff0);
            ldm4(bhi[4], bhi[5], bhi[6], bhi[7], swhi + boff1);
            ldm4(blo[0], blo[1], blo[2], blo[3], swlo + boff0);
            ldm4(blo[4], blo[5], blo[6], blo[7], swlo + boff1);
            #pragma unroll
            for (int tt = 0; tt < 4; tt++) {
                mma16816(acc[tt], ahi, bhi[tt*2], bhi[tt*2+1]);
                mma16816(acc[tt], ahi, blo[tt*2], blo[tt*2+1]);
                mma16816(acc[tt], alo, bhi[tt*2], bhi[tt*2+1]);
            }
        }
    }

    // ---- epilogue: partials [split][b][n] ----
    const int r0 = wm + (l >> 2);
    const int cb = n0 + wn + 2 * (l & 3);
    float* p0 = P + ((size_t)blockIdx.y * 32 + r0) * nrows;
    float* p1 = p0 + (size_t)8 * nrows;
    #pragma unroll
    for (int tt = 0; tt < 4; tt++) {
        *(float2*)(p0 + cb + tt * 8) = make_float2(acc[tt][0], acc[tt][1]);
        *(float2*)(p1 + cb + tt * 8) = make_float2(acc[tt][2], acc[tt][3]);
    }
}

// ============================================================================
// RMSNorm
// ============================================================================
__global__ void rmsnorm_kernel(const float* __restrict__ x,
                               const float* __restrict__ rms_w)
{
    __shared__ float red[256];
    int b = blockIdx.x;
    int tid = threadIdx.x;
    const float* xr = x + b * HID;
    float s = 0.f;
    for (int i = tid; i < HID; i += 256) { float v = xr[i]; s += v * v; }
    red[tid] = s; __syncthreads();
    for (int st = 128; st > 0; st >>= 1) {
        if (tid < st) red[tid] += red[tid + st];
        __syncthreads();
    }
    float rstd = rsqrtf(red[0] / (float)HID + EPS);
    float* o = g_xn + b * HID;
    for (int i = tid; i < HID; i += 256) o[i] = xr[i] * rstd * rms_w[i];
}

// ============================================================================
// Split-K reduce: C = sum_s part[s] (+ addv)
// ============================================================================
template<int S>
__global__ void reduce_split_t(const float* __restrict__ part, int elems,
                               const float* __restrict__ addv,
                               float* __restrict__ C)
{
    int i = blockIdx.x * blockDim.x + threadIdx.x;
    const float4* p = (const float4*)part;
    int q = elems >> 2;
    float4 s = p[i];
    #pragma unroll
    for (int j = 1; j < S; j++) {
        float4 t = p[i + (size_t)j * q];
        s.x += t.x; s.y += t.y; s.z += t.z; s.w += t.w;
    }
    if (addv) {
        float4 a = ((const float4*)addv)[i];
        s.x += a.x; s.y += a.y; s.z += a.z; s.w += a.w;
    }
    ((float4*)C)[i] = s;
}

// ============================================================================
// Conv + fused xm split-4 reduce + silu + new_conv_state
// ============================================================================
__global__ void conv_kernel(const float* __restrict__ conv_state,
                            const float* __restrict__ conv_w,
                            const float* __restrict__ conv_b,
                            const float* __restrict__ xm_part,
                            float* __restrict__ out)
{
    int idx = blockIdx.x * blockDim.x + threadIdx.x;
    if (idx >= BB * INNER) return;
    int c = idx & (INNER - 1);
    float xm = 0.f;
    #pragma unroll
    for (int s = 0; s < 4; s++) xm += xm_part[(size_t)s * BB * INNER + idx];
    const float* cs = conv_state + (size_t)idx * 3;
    float s0 = cs[0], s1 = cs[1], s2 = cs[2];
    const float* w = conv_w + c * 4;
    float xc = s0*w[0] + s1*w[1] + s2*w[2] + xm*w[3] + conv_b[c];
    float* nc = out + CONV_OFF + (size_t)idx * 3;
    nc[0] = s1; nc[1] = s2; nc[2] = xm;
    g_xmc[idx] = xc / (1.f + expf(-xc));
}

// ============================================================================
// Gates
// ============================================================================
__global__ __launch_bounds__(256) void gate_kernel(
    const float* __restrict__ Wi, const float* __restrict__ bi,
    const float* __restrict__ Wf, const float* __restrict__ bf,
    const float* __restrict__ max_state,
    float* __restrict__ out)
{
    __shared__ float ri[256], rf[256];
    int bh = blockIdx.x;
    int h = bh & (NH - 1);
    int b = bh >> 3;
    int tid = threadIdx.x;
    const float4* q4  = (const float4*)(g_qkv + (size_t)b * K3);
    const float4* wi4 = (const float4*)(Wi + (size_t)h * K3);
    const float4* wf4 = (const float4*)(Wf + (size_t)h * K3);
    float si = 0.f, sf = 0.f;
    #pragma unroll
    for (int r = 0; r < K3/4/256; r++) {
        int j = tid + r * 256;
        float4 q = q4[j], a = wi4[j], f = wf4[j];
        si += q.x*a.x + q.y*a.y + q.z*a.z + q.w*a.w;
        sf += q.x*f.x + q.y*f.y + q.z*f.z + q.w*f.w;
    }
    ri[tid] = si; rf[tid] = sf; __syncthreads();
    for (int st = 128; st > 0; st >>= 1) {
        if (tid < st) { ri[tid] += ri[tid+st]; rf[tid] += rf[tid+st]; }
        __syncthreads();
    }
    if (tid == 0) {
        float ig = CAP * tanhf((ri[0] + bi[h]) / CAP);
        float fg = CAP * tanhf((rf[0] + bf[h]) / CAP);
        float lf = (fg >= 0.f) ? -log1pf(expf(-fg)) : (fg - log1pf(expf(fg)));
        float m_old = max_state[bh];
        float m_new = fmaxf(ig, m_old + lf);
        g_ig[bh] = expf(ig - m_new);
        g_fg[bh] = expf(lf + m_old - m_new);
        out[MAX_OFF + bh] = m_new;
    }
}

// ============================================================================
// Cell stream: grid = 4 chunks x 256 bh; 256 threads.
// ============================================================================
__global__ __launch_bounds__(256) void cell_stream(
    const float* __restrict__ cell_state,
    float* __restrict__ out)
{
    __shared__ float qsm[128], ksm[128];
    __shared__ float part[2][HEAD];

    const int bid = blockIdx.x;
    const int bh = bid >> 2;
    const int ch = bid & 3;
    const int h = bh & (NH - 1);
    const int b = bh >> 3;
    const int tid = threadIdx.x;

    const float* qrow = g_qkv + (size_t)b * K3 + h * HEAD;
    const float* krow = qrow + INNER;
    const float* vrow = qrow + 2 * INNER;
    const int d0 = ch * 128;

    if (tid < 128) {
        qsm[tid] = qrow[d0 + tid];
        ksm[tid] = krow[d0 + tid] * KSCALE;
    }
    __syncthreads();

    const float ig = g_ig[bh];
    const float fg = g_fg[bh];

    const int ct = tid & 127;
    const int rg = tid >> 7;
    const int e0 = ct * 4;
    float4 v = *(const float4*)(vrow + e0);
    float4 iv = make_float4(ig*v.x, ig*v.y, ig*v.z, ig*v.w);

    const float* cin  = cell_state + (size_t)bh * HEAD * HEAD;
    float*       cout = out + CELL_OFF + (size_t)bh * HEAD * HEAD;

    float4 nacc = make_float4(0.f, 0.f, 0.f, 0.f);
    #pragma unroll 8
    for (int dd = rg; dd < 128; dd += 2) {
        int d = d0 + dd;
        float4 cv = *(const float4*)(cin + (size_t)d * HEAD + e0);
        float kd = ksm[dd];
        float4 c;
        c.x = fmaf(fg, cv.x, kd * iv.x);
        c.y = fmaf(fg, cv.y, kd * iv.y);
        c.z = fmaf(fg, cv.z, kd * iv.z);
        c.w = fmaf(fg, cv.w, kd * iv.w);
        *(float4*)(cout + (size_t)d * HEAD + e0) = c;
        float qd = qsm[dd];
        nacc.x = fmaf(qd, c.x, nacc.x);
        nacc.y = fmaf(qd, c.y, nacc.y);
        nacc.z = fmaf(qd, c.z, nacc.z);
        nacc.w = fmaf(qd, c.w, nacc.w);
    }
    *(float4*)&part[rg][e0] = nacc;
    __syncthreads();
    if (tid < 128) {
        float4 p0 = *(const float4*)&part[0][e0];
        float4 p1 = *(const float4*)&part[1][e0];
        float4 s = make_float4(p0.x+p1.x, p0.y+p1.y, p0.z+p1.z, p0.w+p1.w);
        *(float4*)(g_numer + (size_t)bid * HEAD + e0) = s;
    }
}

// ============================================================================
// Cell epilogue: norm_new + qn + denom + GroupNorm + gating -> h
// (x_gate split-4 reduce fused)
// ============================================================================
__global__ __launch_bounds__(512) void cell_epi(
    const float* __restrict__ norm_state,
    const float* __restrict__ gn_w, const float* __restrict__ gn_b,
    const float* __restrict__ skip_w,
    const float* __restrict__ xg_part,
    float* __restrict__ out)
{
    __shared__ float red[512];
    const int bh = blockIdx.x;
    const int h = bh & (NH - 1);
    const int b = bh >> 3;
    const int tid = threadIdx.x;

    const float* qrow = g_qkv + (size_t)b * K3 + h * HEAD;
    const float* krow = qrow + INNER;
    float q = qrow[tid];
    float k = krow[tid] * KSCALE;

    const float ig = g_ig[bh];
    const float fg = g_fg[bh];
    const float m_new = out[MAX_OFF + bh];

    float num = g_numer[(size_t)(bh*4+0) * HEAD + tid]
              + g_numer[(size_t)(bh*4+1) * HEAD + tid]
              + g_numer[(size_t)(bh*4+2) * HEAD + tid]
              + g_numer[(size_t)(bh*4+3) * HEAD + tid];

    float nn = fmaf(fg, norm_state[(size_t)bh * HEAD + tid], ig * k);
    out[NORM_OFF + (size_t)bh * HEAD + tid] = nn;

    red[tid] = q * nn; __syncthreads();
    for (int st = 256; st > 0; st >>= 1) {
        if (tid < st) red[tid] += red[tid+st];
        __syncthreads();
    }
    float qn = red[0]; __syncthreads();
    float denom = fmaxf(fabsf(qn), expf(-m_new)) + EPS;
    float o = num / denom;

    red[tid] = o; __syncthreads();
    for (int st = 256; st > 0; st >>= 1) {
        if (tid < st) red[tid] += red[tid+st];
        __syncthreads();
    }
    float mu = red[0] / (float)HEAD; __syncthreads();
    float dv = o - mu;
    red[tid] = dv * dv; __syncthreads();
    for (int st = 256; st > 0; st >>= 1) {
        if (tid < st) red[tid] += red[tid+st];
        __syncthreads();
    }
    float rstd = rsqrtf(red[0] / (float)HEAD + GN_EPS);

    int c = h * HEAD + tid;
    size_t gidx = (size_t)b * INNER + c;
    float xg = 0.f;
    #pragma unroll
    for (int s = 0; s < 4; s++) xg += xg_part[(size_t)s * BB * INNER + gidx];
    float og = fmaf(dv * rstd, gn_w[c], gn_b[c]);
    float sg = xg / (1.f + expf(-xg));
    g_h[gidx] = (og + skip_w[c] * g_xmc[gidx]) * sg;
}

// ============================================================================
extern "C" void kernel_launch(void* const* d_in, const int* in_sizes, int n_in,
                              void* d_out, int out_size)
{
    const float* x          = (const float*)d_in[0];
    const float* conv_state = (const float*)d_in[1];
    const float* cell_state = (const float*)d_in[2];
    const float* norm_state = (const float*)d_in[3];
    const float* max_state  = (const float*)d_in[4];
    const float* rms_w      = (const float*)d_in[5];
    const float* Wx         = (const float*)d_in[6];
    const float* Wg         = (const float*)d_in[7];
    const float* Wqkv       = (const float*)d_in[8];
    const float* conv_w     = (const float*)d_in[9];
    const float* conv_b     = (const float*)d_in[10];
    const float* Wi         = (const float*)d_in[11];
    const float* bi         = (const float*)d_in[12];
    const float* Wf         = (const float*)d_in[13];
    const float* bf         = (const float*)d_in[14];
    const float* gn_w       = (const float*)d_in[15];
    const float* gn_b       = (const float*)d_in[16];
    const float* Wdown      = (const float*)d_in[17];
    const float* skip_w     = (const float*)d_in[18];
    float* out = (float*)d_out;

    float* pxn;   cudaGetSymbolAddress((void**)&pxn,   g_xn);
    float* pxmc;  cudaGetSymbolAddress((void**)&pxmc,  g_xmc);
    float* pqkv;  cudaGetSymbolAddress((void**)&pqkv,  g_qkv);
    float* ph;    cudaGetSymbolAddress((void**)&ph,    g_h);
    float* ppart; cudaGetSymbolAddress((void**)&ppart, g_part);

    // Wg partials: beyond QKV's 4-split region [0, 4*BB*K3)
    float* pp2 = ppart + (size_t)4 * BB * K3;

    cudaFuncSetAttribute(mma_gemm, cudaFuncAttributeMaxDynamicSharedMemorySize,
                         SMEM_MMA);

    // 1) rmsnorm
    rmsnorm_kernel<<<BB, 256>>>(x, rms_w);

    // 2) x_mlstm & x_gate tensor-core GEMM, split-K 4: grid (32+32, 4) = 256
    mma_gemm<<<dim3(64, 4), 256, SMEM_MMA>>>(pxn, Wx, ppart, INNER,
                                             Wg, pp2, INNER, 32, HID, HID/4);

    // 3) conv (fused xm split-4 reduce) + silu + new_conv_state
    conv_kernel<<<(BB*INNER)/256, 256>>>(conv_state, conv_w, conv_b, ppart, out);

    // 4) qkv = xmc @ Wqkv^T, split-K 4: grid (96, 4) = 384
    mma_gemm<<<dim3(96, 4), 256, SMEM_MMA>>>(pxmc, Wqkv, ppart, K3,
                                             Wqkv, ppart, K3, 96, INNER, INNER/4);
    reduce_split_t<4><<<(BB*K3/4)/256, 256>>>(ppart, BB*K3, nullptr, pqkv);

    // 5) gates
    gate_kernel<<<BB*NH, 256>>>(Wi, bi, Wf, bf, max_state, out);

    // 6) cell stream: 1024 blocks
    cell_stream<<<BB*NH*4, 256>>>(cell_state, out);

    // 7) cell epilogue (fused xg reduce) -> h
    cell_epi<<<BB*NH, 512>>>(norm_state, gn_w, gn_b, skip_w, pp2, out);

    // 8) y = h @ Wdown^T + x, split-K 8: grid (16, 8) = 128
    mma_gemm<<<dim3(16, 8), 256, SMEM_MMA>>>(ph, Wdown, ppart, HID,
                                             Wdown, ppart, HID, 16, INNER, INNER/8);
    reduce_split_t<8><<<(BB*HID/4)/256, 256>>>(ppart, BB*HID, x, out + Y_OFF);
}

// round 14
// speedup vs baseline: 1.2833x; 1.0393x over previous
#include <cuda_runtime.h>
#include <cuda_bf16.h>
#include <math.h>
#include <stdint.h>

#define BB 32
#define HID 2048
#define INNER 4096
#define NH 8
#define HEAD 512
#define K3 12288
#define CAP 30.0f
#define EPS 1e-6f
#define GN_EPS 1e-5f
#define KSCALE 0.044194173824159216f   // 1/sqrt(512)

// ---------------- scratch (device globals; no allocs allowed) ----------------
__device__ float g_xn   [BB * HID];
__device__ float g_xg   [BB * INNER];
__device__ float g_xmc  [BB * INNER];
__device__ float g_qkv  [BB * K3];
__device__ float g_h    [BB * INNER];
__device__ float g_part [16 * BB * K3];            // split-K partials
__device__ float g_numer[BB * NH * 4 * HEAD];      // cell numer partials
__device__ float g_ig   [BB * NH];
__device__ float g_fg   [BB * NH];

// ---------------- output layout ----------------
#define Y_OFF    0
#define CONV_OFF 65536
#define CELL_OFF 458752
#define NORM_OFF 67567616
#define MAX_OFF  67698688

// ---------------- mma.sync helpers (sm_80 baseline PTX -> HMMA) -------------
__device__ __forceinline__ unsigned pack2(float c0, float c1) {
    unsigned r;
    asm("cvt.rn.satfinite.bf16x2.f32 %0, %1, %2;" : "=r"(r) : "f"(c1), "f"(c0));
    return r;
}

__device__ __forceinline__ void ldm4(unsigned& r0, unsigned& r1,
                                     unsigned& r2, unsigned& r3, unsigned addr) {
    asm volatile("ldmatrix.sync.aligned.m8n8.x4.shared.b16 {%0,%1,%2,%3}, [%4];"
                 : "=r"(r0), "=r"(r1), "=r"(r2), "=r"(r3) : "r"(addr));
}

__device__ __forceinline__ void mma16816(float* d, const unsigned* a,
                                         unsigned b0, unsigned b1) {
    asm volatile(
        "mma.sync.aligned.m16n8k16.row.col.f32.bf16.bf16.f32 "
        "{%0,%1,%2,%3}, {%4,%5,%6,%7}, {%8,%9}, {%0,%1,%2,%3};"
        : "+f"(d[0]), "+f"(d[1]), "+f"(d[2]), "+f"(d[3])
        : "r"(a[0]), "r"(a[1]), "r"(a[2]), "r"(a[3]), "r"(b0), "r"(b1));
}

__device__ __forceinline__ void cvt_hilo(float4 v, uint2& hi, uint2& lo) {
    unsigned hi01 = pack2(v.x, v.y);
    unsigned hi23 = pack2(v.z, v.w);
    float h0 = __uint_as_float(hi01 << 16);
    float h1 = __uint_as_float(hi01 & 0xFFFF0000u);
    float h2 = __uint_as_float(hi23 << 16);
    float h3 = __uint_as_float(hi23 & 0xFFFF0000u);
    hi = make_uint2(hi01, hi23);
    lo = make_uint2(pack2(v.x - h0, v.y - h1), pack2(v.z - h2, v.w - h3));
}

__device__ __forceinline__ void cp16(void* smem_p, const void* g) {
    unsigned s = (unsigned)__cvta_generic_to_shared(smem_p);
    asm volatile("cp.async.cg.shared.global [%0], [%1], 16;\n" :: "r"(s), "l"(g));
}

// ============================================================================
// MMA GEMM (R11-proven): C[32,N] = A[32,K] @ W[N,K]^T, bf16 hi/lo x3.
// 256 thr, BN=128, BK=32. cp.async 2-deep fp32 staging for BOTH W and A
// -> convert -> bf16 smem -> mma.sync. Warp (of 8): 16m x 32n tile.
// Partial layout: [splitIdx][32][nrows]. Dual-W via nb1.
// ============================================================================
#define SW 40   // bf16 smem row stride (80B) - ldmatrix conflict-free
// dynamic smem offsets (bytes)
#define O_WST 0               // fp32 W stage: 2 * 128*32*4 = 32768
#define O_AST 32768           // fp32 A stage: 2 * 32*32*4  = 8192
#define O_WHI 40960           // 128*SW*2 = 10240
#define O_WLO 51200
#define O_AHI 61440           // 32*SW*2 = 2560
#define O_ALO 64000
#define SMEM_MMA 66560

__global__ __launch_bounds__(256) void mma_gemm(
    const float* __restrict__ A,
    const float* __restrict__ W1, float* __restrict__ P1, int n1,
    const float* __restrict__ W2, float* __restrict__ P2, int n2,
    int nb1, int Kt, int kLen)
{
    extern __shared__ __align__(16) char smem[];
    float* stW = (float*)(smem + O_WST);
    float* stA = (float*)(smem + O_AST);
    __nv_bfloat16* sWhi = (__nv_bfloat16*)(smem + O_WHI);
    __nv_bfloat16* sWlo = (__nv_bfloat16*)(smem + O_WLO);
    __nv_bfloat16* sAhi = (__nv_bfloat16*)(smem + O_AHI);
    __nv_bfloat16* sAlo = (__nv_bfloat16*)(smem + O_ALO);
    const unsigned sbase = (unsigned)__cvta_generic_to_shared(smem);
    const unsigned swhi = sbase + O_WHI;
    const unsigned swlo = sbase + O_WLO;
    const unsigned sahi = sbase + O_AHI;
    const unsigned salo = sbase + O_ALO;

    const int t = threadIdx.x;
    const int bx = blockIdx.x;
    const bool fw = bx < nb1;
    const float* W = fw ? W1 : W2;
    float* P = fw ? P1 : P2;
    const int nrows = fw ? n1 : n2;
    const int n0 = (fw ? bx : bx - nb1) * 128;
    const int kBeg = blockIdx.y * kLen;
    const int NCH = kLen >> 5;

    const int wid = t >> 5, l = t & 31;
    const int wm = (wid & 1) * 16;
    const int wn = (wid >> 1) * 32;

    const int lr = t >> 3;        // 0..31
    const int lc = t & 7;         // float4 col
    const float* wsrc = W + (size_t)(n0 + lr) * Kt + kBeg + lc * 4;
    const float* asrc = A + (size_t)lr * Kt + kBeg + lc * 4;
    const int wsl = lr * 32 + lc * 4;   // stage slot (per 32-row group)
    const int asl = lr * 32 + lc * 4;

    float acc[4][4];
    #pragma unroll
    for (int i = 0; i < 4; i++)
        #pragma unroll
        for (int j = 0; j < 4; j++) acc[i][j] = 0.f;

    // prologue: stage chunks 0,1
    {
        #pragma unroll
        for (int p = 0; p < 4; p++)
            cp16(&stW[p * 1024 + wsl], wsrc + (size_t)(p * 32) * Kt);
        cp16(&stA[asl], asrc);
        asm volatile("cp.async.commit_group;\n");
        if (NCH > 1) {
            #pragma unroll
            for (int p = 0; p < 4; p++)
                cp16(&stW[4096 + p * 1024 + wsl], wsrc + (size_t)(p * 32) * Kt + 32);
            cp16(&stA[1024 + asl], asrc + 32);
            asm volatile("cp.async.commit_group;\n");
        }
    }

    for (int ch = 0; ch < NCH; ch++) {
        const int st = ch & 1;
        if (ch + 1 < NCH) asm volatile("cp.async.wait_group 1;\n");
        else              asm volatile("cp.async.wait_group 0;\n");
        __syncthreads();   // stage ready + prev compute done reading bf16

        // convert fp32 stage -> bf16 hi/lo smem
        #pragma unroll
        for (int p = 0; p < 4; p++) {
            float4 v = *(const float4*)&stW[st * 4096 + p * 1024 + wsl];
            uint2 hi, lo; cvt_hilo(v, hi, lo);
            int bi = (lr + 32 * p) * SW + lc * 4;
            *(uint2*)&sWhi[bi] = hi;
            *(uint2*)&sWlo[bi] = lo;
        }
        {
            float4 v = *(const float4*)&stA[st * 1024 + asl];
            uint2 hi, lo; cvt_hilo(v, hi, lo);
            int bi = lr * SW + lc * 4;
            *(uint2*)&sAhi[bi] = hi;
            *(uint2*)&sAlo[bi] = lo;
        }
        __syncthreads();   // bf16 visible; stage reads complete

        // refill stage st with chunk ch+2
        if (ch + 2 < NCH) {
            #pragma unroll
            for (int p = 0; p < 4; p++)
                cp16(&stW[st * 4096 + p * 1024 + wsl],
                     wsrc + (size_t)(p * 32) * Kt + (ch + 2) * 32);
            cp16(&stA[st * 1024 + asl], asrc + (ch + 2) * 32);
            asm volatile("cp.async.commit_group;\n");
        }

        // compute: 2 k16 steps
        #pragma unroll
        for (int s = 0; s < 2; s++) {
            const int ks = s * 16;
            unsigned arow = wm + ((l >> 3) & 1) * 8 + (l & 7);
            unsigned acol = ks + ((l >> 4) & 1) * 8;
            unsigned aoff = (arow * SW + acol) * 2;
            unsigned ahi[4], alo[4];
            ldm4(ahi[0], ahi[1], ahi[2], ahi[3], sahi + aoff);
            ldm4(alo[0], alo[1], alo[2], alo[3], salo + aoff);
            unsigned brow = wn + ((l >> 4) & 1) * 8 + (l & 7);
            unsigned bcol = ks + ((l >> 3) & 1) * 8;
            unsigned boff0 = (brow * SW + bcol) * 2;
            unsigned boff1 = ((brow + 16) * SW + bcol) * 2;
            unsigned bhi[8], blo[8];
            ldm4(bhi[0], bhi[1], bhi[2], bhi[3], swhi + boff0);
            ldm4(bhi[4], bhi[5], bhi[6], bhi[7], swhi + boff1);
            ldm4(blo[0], blo[1], blo[2], blo[3], swlo + boff0);
            ldm4(blo[4], blo[5], blo[6], blo[7], swlo + boff1);
            #pragma unroll
            for (int tt = 0; tt < 4; tt++) {
                mma16816(acc[tt], ahi, bhi[tt*2], bhi[tt*2+1]);
                mma16816(acc[tt], ahi, blo[tt*2], blo[tt*2+1]);
                mma16816(acc[tt], alo, bhi[tt*2], bhi[tt*2+1]);
            }
        }
    }

    // ---- epilogue: partials [split][b][n] ----
    const int r0 = wm + (l >> 2);
    const int cb = n0 + wn + 2 * (l & 3);
    float* p0 = P + ((size_t)blockIdx.y * 32 + r0) * nrows;
    float* p1 = p0 + (size_t)8 * nrows;
    #pragma unroll
    for (int tt = 0; tt < 4; tt++) {
        *(float2*)(p0 + cb + tt * 8) = make_float2(acc[tt][0], acc[tt][1]);
        *(float2*)(p1 + cb + tt * 8) = make_float2(acc[tt][2], acc[tt][3]);
    }
}

// ============================================================================
// RMSNorm
// ============================================================================
__global__ void rmsnorm_kernel(const float* __restrict__ x,
                               const float* __restrict__ rms_w)
{
    __shared__ float red[256];
    int b = blockIdx.x;
    int tid = threadIdx.x;
    const float* xr = x + b * HID;
    float s = 0.f;
    for (int i = tid; i < HID; i += 256) { float v = xr[i]; s += v * v; }
    red[tid] = s; __syncthreads();
    for (int st = 128; st > 0; st >>= 1) {
        if (tid < st) red[tid] += red[tid + st];
        __syncthreads();
    }
    float rstd = rsqrtf(red[0] / (float)HID + EPS);
    float* o = g_xn + b * HID;
    for (int i = tid; i < HID; i += 256) o[i] = xr[i] * rstd * rms_w[i];
}

// ============================================================================
// Split-K reduce: C = sum_s part[s] (+ addv)
// ============================================================================
template<int S>
__global__ void reduce_split_t(const float* __restrict__ part, int elems,
                               const float* __restrict__ addv,
                               float* __restrict__ C)
{
    int i = blockIdx.x * blockDim.x + threadIdx.x;
    const float4* p = (const float4*)part;
    int q = elems >> 2;
    float4 s = p[i];
    #pragma unroll
    for (int j = 1; j < S; j++) {
        float4 t = p[i + (size_t)j * q];
        s.x += t.x; s.y += t.y; s.z += t.z; s.w += t.w;
    }
    if (addv) {
        float4 a = ((const float4*)addv)[i];
        s.x += a.x; s.y += a.y; s.z += a.z; s.w += a.w;
    }
    ((float4*)C)[i] = s;
}

// ============================================================================
// Conv + fused xm split-4 reduce + silu + new_conv_state
// ============================================================================
__global__ void conv_kernel(const float* __restrict__ conv_state,
                            const float* __restrict__ conv_w,
                            const float* __restrict__ conv_b,
                            const float* __restrict__ xm_part,
                            float* __restrict__ out)
{
    int idx = blockIdx.x * blockDim.x + threadIdx.x;
    if (idx >= BB * INNER) return;
    int c = idx & (INNER - 1);
    float xm = 0.f;
    #pragma unroll
    for (int s = 0; s < 4; s++) xm += xm_part[(size_t)s * BB * INNER + idx];
    const float* cs = conv_state + (size_t)idx * 3;
    float s0 = cs[0], s1 = cs[1], s2 = cs[2];
    const float* w = conv_w + c * 4;
    float xc = s0*w[0] + s1*w[1] + s2*w[2] + xm*w[3] + conv_b[c];
    float* nc = out + CONV_OFF + (size_t)idx * 3;
    nc[0] = s1; nc[1] = s2; nc[2] = xm;
    g_xmc[idx] = xc / (1.f + expf(-xc));
}

// ============================================================================
// Gates
// ============================================================================
__global__ __launch_bounds__(256) void gate_kernel(
    const float* __restrict__ Wi, const float* __restrict__ bi,
    const float* __restrict__ Wf, const float* __restrict__ bf,
    const float* __restrict__ max_state,
    float* __restrict__ out)
{
    __shared__ float ri[256], rf[256];
    int bh = blockIdx.x;
    int h = bh & (NH - 1);
    int b = bh >> 3;
    int tid = threadIdx.x;
    const float4* q4  = (const float4*)(g_qkv + (size_t)b * K3);
    const float4* wi4 = (const float4*)(Wi + (size_t)h * K3);
    const float4* wf4 = (const float4*)(Wf + (size_t)h * K3);
    float si = 0.f, sf = 0.f;
    #pragma unroll
    for (int r = 0; r < K3/4/256; r++) {
        int j = tid + r * 256;
        float4 q = q4[j], a = wi4[j], f = wf4[j];
        si += q.x*a.x + q.y*a.y + q.z*a.z + q.w*a.w;
        sf += q.x*f.x + q.y*f.y + q.z*f.z + q.w*f.w;
    }
    ri[tid] = si; rf[tid] = sf; __syncthreads();
    for (int st = 128; st > 0; st >>= 1) {
        if (tid < st) { ri[tid] += ri[tid+st]; rf[tid] += rf[tid+st]; }
        __syncthreads();
    }
    if (tid == 0) {
        float ig = CAP * tanhf((ri[0] + bi[h]) / CAP);
        float fg = CAP * tanhf((rf[0] + bf[h]) / CAP);
        float lf = (fg >= 0.f) ? -log1pf(expf(-fg)) : (fg - log1pf(expf(fg)));
        float m_old = max_state[bh];
        float m_new = fmaxf(ig, m_old + lf);
        g_ig[bh] = expf(ig - m_new);
        g_fg[bh] = expf(lf + m_old - m_new);
        out[MAX_OFF + bh] = m_new;
    }
}

// ============================================================================
// Cell stream: grid = 4 chunks x 256 bh; 256 threads.
// ============================================================================
__global__ __launch_bounds__(256) void cell_stream(
    const float* __restrict__ cell_state,
    float* __restrict__ out)
{
    __shared__ float qsm[128], ksm[128];
    __shared__ float part[2][HEAD];

    const int bid = blockIdx.x;
    const int bh = bid >> 2;
    const int ch = bid & 3;
    const int h = bh & (NH - 1);
    const int b = bh >> 3;
    const int tid = threadIdx.x;

    const float* qrow = g_qkv + (size_t)b * K3 + h * HEAD;
    const float* krow = qrow + INNER;
    const float* vrow = qrow + 2 * INNER;
    const int d0 = ch * 128;

    if (tid < 128) {
        qsm[tid] = qrow[d0 + tid];
        ksm[tid] = krow[d0 + tid] * KSCALE;
    }
    __syncthreads();

    const float ig = g_ig[bh];
    const float fg = g_fg[bh];

    const int ct = tid & 127;
    const int rg = tid >> 7;
    const int e0 = ct * 4;
    float4 v = *(const float4*)(vrow + e0);
    float4 iv = make_float4(ig*v.x, ig*v.y, ig*v.z, ig*v.w);

    const float* cin  = cell_state + (size_t)bh * HEAD * HEAD;
    float*       cout = out + CELL_OFF + (size_t)bh * HEAD * HEAD;

    float4 nacc = make_float4(0.f, 0.f, 0.f, 0.f);
    #pragma unroll 8
    for (int dd = rg; dd < 128; dd += 2) {
        int d = d0 + dd;
        float4 cv = *(const float4*)(cin + (size_t)d * HEAD + e0);
        float kd = ksm[dd];
        float4 c;
        c.x = fmaf(fg, cv.x, kd * iv.x);
        c.y = fmaf(fg, cv.y, kd * iv.y);
        c.z = fmaf(fg, cv.z, kd * iv.z);
        c.w = fmaf(fg, cv.w, kd * iv.w);
        *(float4*)(cout + (size_t)d * HEAD + e0) = c;
        float qd = qsm[dd];
        nacc.x = fmaf(qd, c.x, nacc.x);
        nacc.y = fmaf(qd, c.y, nacc.y);
        nacc.z = fmaf(qd, c.z, nacc.z);
        nacc.w = fmaf(qd, c.w, nacc.w);
    }
    *(float4*)&part[rg][e0] = nacc;
    __syncthreads();
    if (tid < 128) {
        float4 p0 = *(const float4*)&part[0][e0];
        float4 p1 = *(const float4*)&part[1][e0];
        float4 s = make_float4(p0.x+p1.x, p0.y+p1.y, p0.z+p1.z, p0.w+p1.w);
        *(float4*)(g_numer + (size_t)bid * HEAD + e0) = s;
    }
}

// ============================================================================
// Cell epilogue: norm_new + qn + denom + GroupNorm + gating -> h
// (x_gate split-4 reduce fused)
// ============================================================================
__global__ __launch_bounds__(512) void cell_epi(
    const float* __restrict__ norm_state,
    const float* __restrict__ gn_w, const float* __restrict__ gn_b,
    const float* __restrict__ skip_w,
    const float* __restrict__ xg_part,
    float* __restrict__ out)
{
    __shared__ float red[512];
    const int bh = blockIdx.x;
    const int h = bh & (NH - 1);
    const int b = bh >> 3;
    const int tid = threadIdx.x;

    const float* qrow = g_qkv + (size_t)b * K3 + h * HEAD;
    const float* krow = qrow + INNER;
    float q = qrow[tid];
    float k = krow[tid] * KSCALE;

    const float ig = g_ig[bh];
    const float fg = g_fg[bh];
    const float m_new = out[MAX_OFF + bh];

    float num = g_numer[(size_t)(bh*4+0) * HEAD + tid]
              + g_numer[(size_t)(bh*4+1) * HEAD + tid]
              + g_numer[(size_t)(bh*4+2) * HEAD + tid]
              + g_numer[(size_t)(bh*4+3) * HEAD + tid];

    float nn = fmaf(fg, norm_state[(size_t)bh * HEAD + tid], ig * k);
    out[NORM_OFF + (size_t)bh * HEAD + tid] = nn;

    red[tid] = q * nn; __syncthreads();
    for (int st = 256; st > 0; st >>= 1) {
        if (tid < st) red[tid] += red[tid+st];
        __syncthreads();
    }
    float qn = red[0]; __syncthreads();
    float denom = fmaxf(fabsf(qn), expf(-m_new)) + EPS;
    float o = num / denom;

    red[tid] = o; __syncthreads();
    for (int st = 256; st > 0; st >>= 1) {
        if (tid < st) red[tid] += red[tid+st];
        __syncthreads();
    }
    float mu = red[0] / (float)HEAD; __syncthreads();
    float dv = o - mu;
    red[tid] = dv * dv; __syncthreads();
    for (int st = 256; st > 0; st >>= 1) {
        if (tid < st) red[tid] += red[tid+st];
        __syncthreads();
    }
    float rstd = rsqrtf(red[0] / (float)HEAD + GN_EPS);

    int c = h * HEAD + tid;
    size_t gidx = (size_t)b * INNER + c;
    float xg = 0.f;
    #pragma unroll
    for (int s = 0; s < 4; s++) xg += xg_part[(size_t)s * BB * INNER + gidx];
    float og = fmaf(dv * rstd, gn_w[c], gn_b[c]);
    float sg = xg / (1.f + expf(-xg));
    g_h[gidx] = (og + skip_w[c] * g_xmc[gidx]) * sg;
}

// ============================================================================
extern "C" void kernel_launch(void* const* d_in, const int* in_sizes, int n_in,
                              void* d_out, int out_size)
{
    const float* x          = (const float*)d_in[0];
    const float* conv_state = (const float*)d_in[1];
    const float* cell_state = (const float*)d_in[2];
    const float* norm_state = (const float*)d_in[3];
    const float* max_state  = (const float*)d_in[4];
    const float* rms_w      = (const float*)d_in[5];
    const float* Wx         = (const float*)d_in[6];
    const float* Wg         = (const float*)d_in[7];
    const float* Wqkv       = (const float*)d_in[8];
    const float* conv_w     = (const float*)d_in[9];
    const float* conv_b     = (const float*)d_in[10];
    const float* Wi         = (const float*)d_in[11];
    const float* bi         = (const float*)d_in[12];
    const float* Wf         = (const float*)d_in[13];
    const float* bf         = (const float*)d_in[14];
    const float* gn_w       = (const float*)d_in[15];
    const float* gn_b       = (const float*)d_in[16];
    const float* Wdown      = (const float*)d_in[17];
    const float* skip_w     = (const float*)d_in[18];
    float* out = (float*)d_out;

    float* pxn;   cudaGetSymbolAddress((void**)&pxn,   g_xn);
    float* pxmc;  cudaGetSymbolAddress((void**)&pxmc,  g_xmc);
    float* pqkv;  cudaGetSymbolAddress((void**)&pqkv,  g_qkv);
    float* ph;    cudaGetSymbolAddress((void**)&ph,    g_h);
    float* ppart; cudaGetSymbolAddress((void**)&ppart, g_part);

    // Wg partials: beyond QKV's 4-split region [0, 4*BB*K3)
    float* pp2 = ppart + (size_t)4 * BB * K3;

    cudaFuncSetAttribute(mma_gemm, cudaFuncAttributeMaxDynamicSharedMemorySize,
                         SMEM_MMA);

    // 1) rmsnorm
    rmsnorm_kernel<<<BB, 256>>>(x, rms_w);

    // 2) x_mlstm & x_gate tensor-core GEMM, split-K 4: grid (32+32, 4) = 256
    mma_gemm<<<dim3(64, 4), 256, SMEM_MMA>>>(pxn, Wx, ppart, INNER,
                                             Wg, pp2, INNER, 32, HID, HID/4);

    // 3) conv (fused xm split-4 reduce) + silu + new_conv_state
    conv_kernel<<<(BB*INNER)/256, 256>>>(conv_state, conv_w, conv_b, ppart, out);

    // 4) qkv = xmc @ Wqkv^T, split-K 4: grid (96, 4) = 384
    mma_gemm<<<dim3(96, 4), 256, SMEM_MMA>>>(pxmc, Wqkv, ppart, K3,
                                             Wqkv, ppart, K3, 96, INNER, INNER/4);
    reduce_split_t<4><<<(BB*K3/4)/256, 256>>>(ppart, BB*K3, nullptr, pqkv);

    // 5) gates
    gate_kernel<<<BB*NH, 256>>>(Wi, bi, Wf, bf, max_state, out);

    // 6) cell stream: 1024 blocks
    cell_stream<<<BB*NH*4, 256>>>(cell_state, out);

    // 7) cell epilogue (fused xg reduce) -> h
    cell_epi<<<BB*NH, 512>>>(norm_state, gn_w, gn_b, skip_w, pp2, out);

    // 8) y = h @ Wdown^T + x, split-K 16: grid (16, 16) = 256
    mma_gemm<<<dim3(16, 16), 256, SMEM_MMA>>>(ph, Wdown, ppart, HID,
                                              Wdown, ppart, HID, 16, INNER, INNER/16);
    reduce_split_t<16><<<(BB*HID/4)/256, 256>>>(ppart, BB*HID, x, out + Y_OFF);
}

// round 15
// speedup vs baseline: 1.2853x; 1.0015x over previous
#include <cuda_runtime.h>
#include <cuda_bf16.h>
#include <math.h>
#include <stdint.h>

#define BB 32
#define HID 2048
#define INNER 4096
#define NH 8
#define HEAD 512
#define K3 12288
#define CAP 30.0f
#define EPS 1e-6f
#define GN_EPS 1e-5f
#define KSCALE 0.044194173824159216f   // 1/sqrt(512)

// ---------------- scratch (device globals; no allocs allowed) ----------------
__device__ float g_xn   [BB * HID];
__device__ float g_xg   [BB * INNER];
__device__ float g_xmc  [BB * INNER];
__device__ float g_qkv  [BB * K3];
__device__ float g_h    [BB * INNER];
__device__ float g_part [16 * BB * K3];            // split-K partials
__device__ float g_numer[BB * NH * 4 * HEAD];      // cell numer partials
__device__ float g_ig   [BB * NH];
__device__ float g_fg   [BB * NH];

// ---------------- output layout ----------------
#define Y_OFF    0
#define CONV_OFF 65536
#define CELL_OFF 458752
#define NORM_OFF 67567616
#define MAX_OFF  67698688

// ---------------- mma.sync helpers (sm_80 baseline PTX -> HMMA) -------------
__device__ __forceinline__ unsigned pack2(float c0, float c1) {
    unsigned r;
    asm("cvt.rn.satfinite.bf16x2.f32 %0, %1, %2;" : "=r"(r) : "f"(c1), "f"(c0));
    return r;
}

__device__ __forceinline__ void ldm4(unsigned& r0, unsigned& r1,
                                     unsigned& r2, unsigned& r3, unsigned addr) {
    asm volatile("ldmatrix.sync.aligned.m8n8.x4.shared.b16 {%0,%1,%2,%3}, [%4];"
                 : "=r"(r0), "=r"(r1), "=r"(r2), "=r"(r3) : "r"(addr));
}

__device__ __forceinline__ void mma16816(float* d, const unsigned* a,
                                         unsigned b0, unsigned b1) {
    asm volatile(
        "mma.sync.aligned.m16n8k16.row.col.f32.bf16.bf16.f32 "
        "{%0,%1,%2,%3}, {%4,%5,%6,%7}, {%8,%9}, {%0,%1,%2,%3};"
        : "+f"(d[0]), "+f"(d[1]), "+f"(d[2]), "+f"(d[3])
        : "r"(a[0]), "r"(a[1]), "r"(a[2]), "r"(a[3]), "r"(b0), "r"(b1));
}

__device__ __forceinline__ void cvt_hilo(float4 v, uint2& hi, uint2& lo) {
    unsigned hi01 = pack2(v.x, v.y);
    unsigned hi23 = pack2(v.z, v.w);
    float h0 = __uint_as_float(hi01 << 16);
    float h1 = __uint_as_float(hi01 & 0xFFFF0000u);
    float h2 = __uint_as_float(hi23 << 16);
    float h3 = __uint_as_float(hi23 & 0xFFFF0000u);
    hi = make_uint2(hi01, hi23);
    lo = make_uint2(pack2(v.x - h0, v.y - h1), pack2(v.z - h2, v.w - h3));
}

__device__ __forceinline__ void cp16(void* smem_p, const void* g) {
    unsigned s = (unsigned)__cvta_generic_to_shared(smem_p);
    asm volatile("cp.async.cg.shared.global [%0], [%1], 16;\n" :: "r"(s), "l"(g));
}

// ============================================================================
// MMA GEMM (R11-proven): C[32,N] = A[32,K] @ W[N,K]^T, bf16 hi/lo x3.
// 256 thr, BN=128, BK=32. cp.async 2-deep fp32 staging for BOTH W and A
// -> convert -> bf16 smem -> mma.sync. Warp (of 8): 16m x 32n tile.
// Partial layout: [splitIdx][32][nrows]. Dual-W via nb1.
// ============================================================================
#define SW 40   // bf16 smem row stride (80B) - ldmatrix conflict-free
// dynamic smem offsets (bytes)
#define O_WST 0               // fp32 W stage: 2 * 128*32*4 = 32768
#define O_AST 32768           // fp32 A stage: 2 * 32*32*4  = 8192
#define O_WHI 40960           // 128*SW*2 = 10240
#define O_WLO 51200
#define O_AHI 61440           // 32*SW*2 = 2560
#define O_ALO 64000
#define SMEM_MMA 66560

__global__ __launch_bounds__(256) void mma_gemm(
    const float* __restrict__ A,
    const float* __restrict__ W1, float* __restrict__ P1, int n1,
    const float* __restrict__ W2, float* __restrict__ P2, int n2,
    int nb1, int Kt, int kLen)
{
    extern __shared__ __align__(16) char smem[];
    float* stW = (float*)(smem + O_WST);
    float* stA = (float*)(smem + O_AST);
    __nv_bfloat16* sWhi = (__nv_bfloat16*)(smem + O_WHI);
    __nv_bfloat16* sWlo = (__nv_bfloat16*)(smem + O_WLO);
    __nv_bfloat16* sAhi = (__nv_bfloat16*)(smem + O_AHI);
    __nv_bfloat16* sAlo = (__nv_bfloat16*)(smem + O_ALO);
    const unsigned sbase = (unsigned)__cvta_generic_to_shared(smem);
    const unsigned swhi = sbase + O_WHI;
    const unsigned swlo = sbase + O_WLO;
    const unsigned sahi = sbase + O_AHI;
    const unsigned salo = sbase + O_ALO;

    const int t = threadIdx.x;
    const int bx = blockIdx.x;
    const bool fw = bx < nb1;
    const float* W = fw ? W1 : W2;
    float* P = fw ? P1 : P2;
    const int nrows = fw ? n1 : n2;
    const int n0 = (fw ? bx : bx - nb1) * 128;
    const int kBeg = blockIdx.y * kLen;
    const int NCH = kLen >> 5;

    const int wid = t >> 5, l = t & 31;
    const int wm = (wid & 1) * 16;
    const int wn = (wid >> 1) * 32;

    const int lr = t >> 3;        // 0..31
    const int lc = t & 7;         // float4 col
    const float* wsrc = W + (size_t)(n0 + lr) * Kt + kBeg + lc * 4;
    const float* asrc = A + (size_t)lr * Kt + kBeg + lc * 4;
    const int wsl = lr * 32 + lc * 4;   // stage slot (per 32-row group)
    const int asl = lr * 32 + lc * 4;

    float acc[4][4];
    #pragma unroll
    for (int i = 0; i < 4; i++)
        #pragma unroll
        for (int j = 0; j < 4; j++) acc[i][j] = 0.f;

    // prologue: stage chunks 0,1
    {
        #pragma unroll
        for (int p = 0; p < 4; p++)
            cp16(&stW[p * 1024 + wsl], wsrc + (size_t)(p * 32) * Kt);
        cp16(&stA[asl], asrc);
        asm volatile("cp.async.commit_group;\n");
        if (NCH > 1) {
            #pragma unroll
            for (int p = 0; p < 4; p++)
                cp16(&stW[4096 + p * 1024 + wsl], wsrc + (size_t)(p * 32) * Kt + 32);
            cp16(&stA[1024 + asl], asrc + 32);
            asm volatile("cp.async.commit_group;\n");
        }
    }

    for (int ch = 0; ch < NCH; ch++) {
        const int st = ch & 1;
        if (ch + 1 < NCH) asm volatile("cp.async.wait_group 1;\n");
        else              asm volatile("cp.async.wait_group 0;\n");
        __syncthreads();   // stage ready + prev compute done reading bf16

        // convert fp32 stage -> bf16 hi/lo smem
        #pragma unroll
        for (int p = 0; p < 4; p++) {
            float4 v = *(const float4*)&stW[st * 4096 + p * 1024 + wsl];
            uint2 hi, lo; cvt_hilo(v, hi, lo);
            int bi = (lr + 32 * p) * SW + lc * 4;
            *(uint2*)&sWhi[bi] = hi;
            *(uint2*)&sWlo[bi] = lo;
        }
        {
            float4 v = *(const float4*)&stA[st * 1024 + asl];
            uint2 hi, lo; cvt_hilo(v, hi, lo);
            int bi = lr * SW + lc * 4;
            *(uint2*)&sAhi[bi] = hi;
            *(uint2*)&sAlo[bi] = lo;
        }
        __syncthreads();   // bf16 visible; stage reads complete

        // refill stage st with chunk ch+2
        if (ch + 2 < NCH) {
            #pragma unroll
            for (int p = 0; p < 4; p++)
                cp16(&stW[st * 4096 + p * 1024 + wsl],
                     wsrc + (size_t)(p * 32) * Kt + (ch + 2) * 32);
            cp16(&stA[st * 1024 + asl], asrc + (ch + 2) * 32);
            asm volatile("cp.async.commit_group;\n");
        }

        // compute: 2 k16 steps
        #pragma unroll
        for (int s = 0; s < 2; s++) {
            const int ks = s * 16;
            unsigned arow = wm + ((l >> 3) & 1) * 8 + (l & 7);
            unsigned acol = ks + ((l >> 4) & 1) * 8;
            unsigned aoff = (arow * SW + acol) * 2;
            unsigned ahi[4], alo[4];
            ldm4(ahi[0], ahi[1], ahi[2], ahi[3], sahi + aoff);
            ldm4(alo[0], alo[1], alo[2], alo[3], salo + aoff);
            unsigned brow = wn + ((l >> 4) & 1) * 8 + (l & 7);
            unsigned bcol = ks + ((l >> 3) & 1) * 8;
            unsigned boff0 = (brow * SW + bcol) * 2;
            unsigned boff1 = ((brow + 16) * SW + bcol) * 2;
            unsigned bhi[8], blo[8];
            ldm4(bhi[0], bhi[1], bhi[2], bhi[3], swhi + boff0);
            ldm4(bhi[4], bhi[5], bhi[6], bhi[7], swhi + boff1);
            ldm4(blo[0], blo[1], blo[2], blo[3], swlo + boff0);
            ldm4(blo[4], blo[5], blo[6], blo[7], swlo + boff1);
            #pragma unroll
            for (int tt = 0; tt < 4; tt++) {
                mma16816(acc[tt], ahi, bhi[tt*2], bhi[tt*2+1]);
                mma16816(acc[tt], ahi, blo[tt*2], blo[tt*2+1]);
                mma16816(acc[tt], alo, bhi[tt*2], bhi[tt*2+1]);
            }
        }
    }

    // ---- epilogue: partials [split][b][n] ----
    const int r0 = wm + (l >> 2);
    const int cb = n0 + wn + 2 * (l & 3);
    float* p0 = P + ((size_t)blockIdx.y * 32 + r0) * nrows;
    float* p1 = p0 + (size_t)8 * nrows;
    #pragma unroll
    for (int tt = 0; tt < 4; tt++) {
        *(float2*)(p0 + cb + tt * 8) = make_float2(acc[tt][0], acc[tt][1]);
        *(float2*)(p1 + cb + tt * 8) = make_float2(acc[tt][2], acc[tt][3]);
    }
}

// ============================================================================
// RMSNorm
// ============================================================================
__global__ void rmsnorm_kernel(const float* __restrict__ x,
                               const float* __restrict__ rms_w)
{
    __shared__ float red[256];
    int b = blockIdx.x;
    int tid = threadIdx.x;
    const float* xr = x + b * HID;
    float s = 0.f;
    for (int i = tid; i < HID; i += 256) { float v = xr[i]; s += v * v; }
    red[tid] = s; __syncthreads();
    for (int st = 128; st > 0; st >>= 1) {
        if (tid < st) red[tid] += red[tid + st];
        __syncthreads();
    }
    float rstd = rsqrtf(red[0] / (float)HID + EPS);
    float* o = g_xn + b * HID;
    for (int i = tid; i < HID; i += 256) o[i] = xr[i] * rstd * rms_w[i];
}

// ============================================================================
// Split-K reduce: C = sum_s part[s] (+ addv)
// ============================================================================
template<int S>
__global__ void reduce_split_t(const float* __restrict__ part, int elems,
                               const float* __restrict__ addv,
                               float* __restrict__ C)
{
    int i = blockIdx.x * blockDim.x + threadIdx.x;
    const float4* p = (const float4*)part;
    int q = elems >> 2;
    float4 s = p[i];
    #pragma unroll
    for (int j = 1; j < S; j++) {
        float4 t = p[i + (size_t)j * q];
        s.x += t.x; s.y += t.y; s.z += t.z; s.w += t.w;
    }
    if (addv) {
        float4 a = ((const float4*)addv)[i];
        s.x += a.x; s.y += a.y; s.z += a.z; s.w += a.w;
    }
    ((float4*)C)[i] = s;
}

// ============================================================================
// Conv + fused xm split-4 reduce + silu + new_conv_state  (4 channels/thread)
// ============================================================================
__global__ void conv_kernel(const float* __restrict__ conv_state,
                            const float* __restrict__ conv_w,
                            const float* __restrict__ conv_b,
                            const float* __restrict__ xm_part,
                            float* __restrict__ out)
{
    int i4 = blockIdx.x * blockDim.x + threadIdx.x;
    if (i4 >= BB * INNER / 4) return;
    int idx = i4 * 4;                 // b*INNER + c, multiple of 4
    int c = idx & (INNER - 1);

    // xm split-4 reduce (float4)
    float4 xm = make_float4(0.f, 0.f, 0.f, 0.f);
    #pragma unroll
    for (int s = 0; s < 4; s++) {
        float4 tpt = *(const float4*)(xm_part + (size_t)s * BB * INNER + idx);
        xm.x += tpt.x; xm.y += tpt.y; xm.z += tpt.z; xm.w += tpt.w;
    }

    // conv_state: 4 channels x 3 = 12 floats = 3 float4
    const float4* cs = (const float4*)(conv_state + (size_t)idx * 3);
    float4 f0 = cs[0], f1 = cs[1], f2 = cs[2];
    // c0: {f0.x,f0.y,f0.z}  c1: {f0.w,f1.x,f1.y}
    // c2: {f1.z,f1.w,f2.x}  c3: {f2.y,f2.z,f2.w}
    const float4* w4 = (const float4*)(conv_w + c * 4);
    float4 w0 = w4[0], w1 = w4[1], w2 = w4[2], w3 = w4[3];
    float4 cb = *(const float4*)(conv_b + c);

    float xc0 = f0.x*w0.x + f0.y*w0.y + f0.z*w0.z + xm.x*w0.w + cb.x;
    float xc1 = f0.w*w1.x + f1.x*w1.y + f1.y*w1.z + xm.y*w1.w + cb.y;
    float xc2 = f1.z*w2.x + f1.w*w2.y + f2.x*w2.z + xm.z*w2.w + cb.z;
    float xc3 = f2.y*w3.x + f2.z*w3.y + f2.w*w3.z + xm.w*w3.w + cb.w;

    // new conv state per channel: {s1, s2, xm}
    float4* nc = (float4*)(out + CONV_OFF + (size_t)idx * 3);
    nc[0] = make_float4(f0.y, f0.z, xm.x, f1.x);
    nc[1] = make_float4(f1.y, xm.y, f1.w, f2.x);
    nc[2] = make_float4(xm.z, f2.z, f2.w, xm.w);

    float4 o;
    o.x = xc0 / (1.f + expf(-xc0));
    o.y = xc1 / (1.f + expf(-xc1));
    o.z = xc2 / (1.f + expf(-xc2));
    o.w = xc3 / (1.f + expf(-xc3));
    *(float4*)&g_xmc[idx] = o;
}

// ============================================================================
// Gates
// ============================================================================
__global__ __launch_bounds__(256) void gate_kernel(
    const float* __restrict__ Wi, const float* __restrict__ bi,
    const float* __restrict__ Wf, const float* __restrict__ bf,
    const float* __restrict__ max_state,
    float* __restrict__ out)
{
    __shared__ float ri[256], rf[256];
    int bh = blockIdx.x;
    int h = bh & (NH - 1);
    int b = bh >> 3;
    int tid = threadIdx.x;
    const float4* q4  = (const float4*)(g_qkv + (size_t)b * K3);
    const float4* wi4 = (const float4*)(Wi + (size_t)h * K3);
    const float4* wf4 = (const float4*)(Wf + (size_t)h * K3);
    float si = 0.f, sf = 0.f;
    #pragma unroll
    for (int r = 0; r < K3/4/256; r++) {
        int j = tid + r * 256;
        float4 q = q4[j], a = wi4[j], f = wf4[j];
        si += q.x*a.x + q.y*a.y + q.z*a.z + q.w*a.w;
        sf += q.x*f.x + q.y*f.y + q.z*f.z + q.w*f.w;
    }
    ri[tid] = si; rf[tid] = sf; __syncthreads();
    for (int st = 128; st > 0; st >>= 1) {
        if (tid < st) { ri[tid] += ri[tid+st]; rf[tid] += rf[tid+st]; }
        __syncthreads();
    }
    if (tid == 0) {
        float ig = CAP * tanhf((ri[0] + bi[h]) / CAP);
        float fg = CAP * tanhf((rf[0] + bf[h]) / CAP);
        float lf = (fg >= 0.f) ? -log1pf(expf(-fg)) : (fg - log1pf(expf(fg)));
        float m_old = max_state[bh];
        float m_new = fmaxf(ig, m_old + lf);
        g_ig[bh] = expf(ig - m_new);
        g_fg[bh] = expf(lf + m_old - m_new);
        out[MAX_OFF + bh] = m_new;
    }
}

// ============================================================================
// Cell stream: grid = 4 chunks x 256 bh; 256 threads.
// ============================================================================
__global__ __launch_bounds__(256) void cell_stream(
    const float* __restrict__ cell_state,
    float* __restrict__ out)
{
    __shared__ float qsm[128], ksm[128];
    __shared__ float part[2][HEAD];

    const int bid = blockIdx.x;
    const int bh = bid >> 2;
    const int ch = bid & 3;
    const int h = bh & (NH - 1);
    const int b = bh >> 3;
    const int tid = threadIdx.x;

    const float* qrow = g_qkv + (size_t)b * K3 + h * HEAD;
    const float* krow = qrow + INNER;
    const float* vrow = qrow + 2 * INNER;
    const int d0 = ch * 128;

    if (tid < 128) {
        qsm[tid] = qrow[d0 + tid];
        ksm[tid] = krow[d0 + tid] * KSCALE;
    }
    __syncthreads();

    const float ig = g_ig[bh];
    const float fg = g_fg[bh];

    const int ct = tid & 127;
    const int rg = tid >> 7;
    const int e0 = ct * 4;
    float4 v = *(const float4*)(vrow + e0);
    float4 iv = make_float4(ig*v.x, ig*v.y, ig*v.z, ig*v.w);

    const float* cin  = cell_state + (size_t)bh * HEAD * HEAD;
    float*       cout = out + CELL_OFF + (size_t)bh * HEAD * HEAD;

    float4 nacc = make_float4(0.f, 0.f, 0.f, 0.f);
    #pragma unroll 8
    for (int dd = rg; dd < 128; dd += 2) {
        int d = d0 + dd;
        float4 cv = *(const float4*)(cin + (size_t)d * HEAD + e0);
        float kd = ksm[dd];
        float4 c;
        c.x = fmaf(fg, cv.x, kd * iv.x);
        c.y = fmaf(fg, cv.y, kd * iv.y);
        c.z = fmaf(fg, cv.z, kd * iv.z);
        c.w = fmaf(fg, cv.w, kd * iv.w);
        *(float4*)(cout + (size_t)d * HEAD + e0) = c;
        float qd = qsm[dd];
        nacc.x = fmaf(qd, c.x, nacc.x);
        nacc.y = fmaf(qd, c.y, nacc.y);
        nacc.z = fmaf(qd, c.z, nacc.z);
        nacc.w = fmaf(qd, c.w, nacc.w);
    }
    *(float4*)&part[rg][e0] = nacc;
    __syncthreads();
    if (tid < 128) {
        float4 p0 = *(const float4*)&part[0][e0];
        float4 p1 = *(const float4*)&part[1][e0];
        float4 s = make_float4(p0.x+p1.x, p0.y+p1.y, p0.z+p1.z, p0.w+p1.w);
        *(float4*)(g_numer + (size_t)bid * HEAD + e0) = s;
    }
}

// ============================================================================
// Cell epilogue: norm_new + qn + denom + GroupNorm + gating -> h
// (x_gate split-4 reduce fused)
// ============================================================================
__global__ __launch_bounds__(512) void cell_epi(
    const float* __restrict__ norm_state,
    const float* __restrict__ gn_w, const float* __restrict__ gn_b,
    const float* __restrict__ skip_w,
    const float* __restrict__ xg_part,
    float* __restrict__ out)
{
    __shared__ float red[512];
    const int bh = blockIdx.x;
    const int h = bh & (NH - 1);
    const int b = bh >> 3;
    const int tid = threadIdx.x;

    const float* qrow = g_qkv + (size_t)b * K3 + h * HEAD;
    const float* krow = qrow + INNER;
    float q = qrow[tid];
    float k = krow[tid] * KSCALE;

    const float ig = g_ig[bh];
    const float fg = g_fg[bh];
    const float m_new = out[MAX_OFF + bh];

    float num = g_numer[(size_t)(bh*4+0) * HEAD + tid]
              + g_numer[(size_t)(bh*4+1) * HEAD + tid]
              + g_numer[(size_t)(bh*4+2) * HEAD + tid]
              + g_numer[(size_t)(bh*4+3) * HEAD + tid];

    float nn = fmaf(fg, norm_state[(size_t)bh * HEAD + tid], ig * k);
    out[NORM_OFF + (size_t)bh * HEAD + tid] = nn;

    red[tid] = q * nn; __syncthreads();
    for (int st = 256; st > 0; st >>= 1) {
        if (tid < st) red[tid] += red[tid+st];
        __syncthreads();
    }
    float qn = red[0]; __syncthreads();
    float denom = fmaxf(fabsf(qn), expf(-m_new)) + EPS;
    float o = num / denom;

    red[tid] = o; __syncthreads();
    for (int st = 256; st > 0; st >>= 1) {
        if (tid < st) red[tid] += red[tid+st];
        __syncthreads();
    }
    float mu = red[0] / (float)HEAD; __syncthreads();
    float dv = o - mu;
    red[tid] = dv * dv; __syncthreads();
    for (int st = 256; st > 0; st >>= 1) {
        if (tid < st) red[tid] += red[tid+st];
        __syncthreads();
    }
    float rstd = rsqrtf(red[0] / (float)HEAD + GN_EPS);

    int c = h * HEAD + tid;
    size_t gidx = (size_t)b * INNER + c;
    float xg = 0.f;
    #pragma unroll
    for (int s = 0; s < 4; s++) xg += xg_part[(size_t)s * BB * INNER + gidx];
    float og = fmaf(dv * rstd, gn_w[c], gn_b[c]);
    float sg = xg / (1.f + expf(-xg));
    g_h[gidx] = (og + skip_w[c] * g_xmc[gidx]) * sg;
}

// ============================================================================
extern "C" void kernel_launch(void* const* d_in, const int* in_sizes, int n_in,
                              void* d_out, int out_size)
{
    const float* x          = (const float*)d_in[0];
    const float* conv_state = (const float*)d_in[1];
    const float* cell_state = (const float*)d_in[2];
    const float* norm_state = (const float*)d_in[3];
    const float* max_state  = (const float*)d_in[4];
    const float* rms_w      = (const float*)d_in[5];
    const float* Wx         = (const float*)d_in[6];
    const float* Wg         = (const float*)d_in[7];
    const float* Wqkv       = (const float*)d_in[8];
    const float* conv_w     = (const float*)d_in[9];
    const float* conv_b     = (const float*)d_in[10];
    const float* Wi         = (const float*)d_in[11];
    const float* bi         = (const float*)d_in[12];
    const float* Wf         = (const float*)d_in[13];
    const float* bf         = (const float*)d_in[14];
    const float* gn_w       = (const float*)d_in[15];
    const float* gn_b       = (const float*)d_in[16];
    const float* Wdown      = (const float*)d_in[17];
    const float* skip_w     = (const float*)d_in[18];
    float* out = (float*)d_out;

    float* pxn;   cudaGetSymbolAddress((void**)&pxn,   g_xn);
    float* pxmc;  cudaGetSymbolAddress((void**)&pxmc,  g_xmc);
    float* pqkv;  cudaGetSymbolAddress((void**)&pqkv,  g_qkv);
    float* ph;    cudaGetSymbolAddress((void**)&ph,    g_h);
    float* ppart; cudaGetSymbolAddress((void**)&ppart, g_part);

    // Wg partials: beyond QKV's 4-split region [0, 4*BB*K3)
    float* pp2 = ppart + (size_t)4 * BB * K3;

    cudaFuncSetAttribute(mma_gemm, cudaFuncAttributeMaxDynamicSharedMemorySize,
                         SMEM_MMA);
    // request max smem carveout so 3 CTAs/SM can be resident
    cudaFuncSetAttribute(mma_gemm, cudaFuncAttributePreferredSharedMemoryCarveout,
                         100);

    // 1) rmsnorm
    rmsnorm_kernel<<<BB, 256>>>(x, rms_w);

    // 2) x_mlstm & x_gate tensor-core GEMM, split-K 4: grid (32+32, 4) = 256
    mma_gemm<<<dim3(64, 4), 256, SMEM_MMA>>>(pxn, Wx, ppart, INNER,
                                             Wg, pp2, INNER, 32, HID, HID/4);

    // 3) conv (fused xm split-4 reduce) + silu + new_conv_state
    conv_kernel<<<(BB*INNER/4)/256, 256>>>(conv_state, conv_w, conv_b, ppart, out);

    // 4) qkv = xmc @ Wqkv^T, split-K 4: grid (96, 4) = 384
    mma_gemm<<<dim3(96, 4), 256, SMEM_MMA>>>(pxmc, Wqkv, ppart, K3,
                                             Wqkv, ppart, K3, 96, INNER, INNER/4);
    reduce_split_t<4><<<(BB*K3/4)/256, 256>>>(ppart, BB*K3, nullptr, pqkv);

    // 5) gates
    gate_kernel<<<BB*NH, 256>>>(Wi, bi, Wf, bf, max_state, out);

    // 6) cell stream: 1024 blocks
    cell_stream<<<BB*NH*4, 256>>>(cell_state, out);

    // 7) cell epilogue (fused xg reduce) -> h
    cell_epi<<<BB*NH, 512>>>(norm_state, gn_w, gn_b, skip_w, pp2, out);

    // 8) y = h @ Wdown^T + x, split-K 16: grid (16, 16) = 256
    mma_gemm<<<dim3(16, 16), 256, SMEM_MMA>>>(ph, Wdown, ppart, HID,
                                              Wdown, ppart, HID, 16, INNER, INNER/16);
    reduce_split_t<16><<<(BB*HID/4)/256, 256>>>(ppart, BB*HID, x, out + Y_OFF);
}

// round 16
// speedup vs baseline: 1.3045x; 1.0149x over previous
#include <cuda_runtime.h>
#include <cuda_bf16.h>
#include <math.h>
#include <stdint.h>

#define BB 32
#define HID 2048
#define INNER 4096
#define NH 8
#define HEAD 512
#define K3 12288
#define CAP 30.0f
#define EPS 1e-6f
#define GN_EPS 1e-5f
#define KSCALE 0.044194173824159216f   // 1/sqrt(512)

// ---------------- scratch (device globals; no allocs allowed) ----------------
__device__ float g_xn   [BB * HID];
__device__ float g_xg   [BB * INNER];
__device__ float g_xmc  [BB * INNER];
__device__ float g_qkv  [BB * K3];
__device__ float g_h    [BB * INNER];
__device__ float g_part [16 * BB * K3];            // split-K partials
__device__ float g_numer[BB * NH * 4 * HEAD];      // cell numer partials
__device__ float g_ig   [BB * NH];
__device__ float g_fg   [BB * NH];

// ---------------- output layout ----------------
#define Y_OFF    0
#define CONV_OFF 65536
#define CELL_OFF 458752
#define NORM_OFF 67567616
#define MAX_OFF  67698688

// ---------------- mma.sync helpers (sm_80 baseline PTX -> HMMA) -------------
__device__ __forceinline__ unsigned pack2(float c0, float c1) {
    unsigned r;
    asm("cvt.rn.satfinite.bf16x2.f32 %0, %1, %2;" : "=r"(r) : "f"(c1), "f"(c0));
    return r;
}

__device__ __forceinline__ void ldm4(unsigned& r0, unsigned& r1,
                                     unsigned& r2, unsigned& r3, unsigned addr) {
    asm volatile("ldmatrix.sync.aligned.m8n8.x4.shared.b16 {%0,%1,%2,%3}, [%4];"
                 : "=r"(r0), "=r"(r1), "=r"(r2), "=r"(r3) : "r"(addr));
}

__device__ __forceinline__ void mma16816(float* d, const unsigned* a,
                                         unsigned b0, unsigned b1) {
    asm volatile(
        "mma.sync.aligned.m16n8k16.row.col.f32.bf16.bf16.f32 "
        "{%0,%1,%2,%3}, {%4,%5,%6,%7}, {%8,%9}, {%0,%1,%2,%3};"
        : "+f"(d[0]), "+f"(d[1]), "+f"(d[2]), "+f"(d[3])
        : "r"(a[0]), "r"(a[1]), "r"(a[2]), "r"(a[3]), "r"(b0), "r"(b1));
}

__device__ __forceinline__ void cvt_hilo(float4 v, uint2& hi, uint2& lo) {
    unsigned hi01 = pack2(v.x, v.y);
    unsigned hi23 = pack2(v.z, v.w);
    float h0 = __uint_as_float(hi01 << 16);
    float h1 = __uint_as_float(hi01 & 0xFFFF0000u);
    float h2 = __uint_as_float(hi23 << 16);
    float h3 = __uint_as_float(hi23 & 0xFFFF0000u);
    hi = make_uint2(hi01, hi23);
    lo = make_uint2(pack2(v.x - h0, v.y - h1), pack2(v.z - h2, v.w - h3));
}

__device__ __forceinline__ void cp16(void* smem_p, const void* g) {
    unsigned s = (unsigned)__cvta_generic_to_shared(smem_p);
    asm volatile("cp.async.cg.shared.global [%0], [%1], 16;\n" :: "r"(s), "l"(g));
}

// ============================================================================
// MMA GEMM: C[32,N] = A[32,K] @ W[N,K]^T, bf16 hi/lo x3, uneven split-K.
// 256 thr, BN=128, BK=32. cp.async 2-deep fp32 staging for BOTH W and A
// -> convert -> bf16 smem -> mma.sync. Warp (of 8): 16m x 32n tile.
// K-split over 32-wide tiles: split 'by' handles base+(by<rem) tiles.
// Partial layout: [splitIdx][32][nrows]. Dual-W via nb1.
// ============================================================================
#define SW 40   // bf16 smem row stride (80B) - ldmatrix conflict-free
// dynamic smem offsets (bytes)
#define O_WST 0               // fp32 W stage: 2 * 128*32*4 = 32768
#define O_AST 32768           // fp32 A stage: 2 * 32*32*4  = 8192
#define O_WHI 40960           // 128*SW*2 = 10240
#define O_WLO 51200
#define O_AHI 61440           // 32*SW*2 = 2560
#define O_ALO 64000
#define SMEM_MMA 66560

__global__ __launch_bounds__(256) void mma_gemm(
    const float* __restrict__ A,
    const float* __restrict__ W1, float* __restrict__ P1, int n1,
    const float* __restrict__ W2, float* __restrict__ P2, int n2,
    int nb1, int Kt)
{
    extern __shared__ __align__(16) char smem[];
    float* stW = (float*)(smem + O_WST);
    float* stA = (float*)(smem + O_AST);
    __nv_bfloat16* sWhi = (__nv_bfloat16*)(smem + O_WHI);
    __nv_bfloat16* sWlo = (__nv_bfloat16*)(smem + O_WLO);
    __nv_bfloat16* sAhi = (__nv_bfloat16*)(smem + O_AHI);
    __nv_bfloat16* sAlo = (__nv_bfloat16*)(smem + O_ALO);
    const unsigned sbase = (unsigned)__cvta_generic_to_shared(smem);
    const unsigned swhi = sbase + O_WHI;
    const unsigned swlo = sbase + O_WLO;
    const unsigned sahi = sbase + O_AHI;
    const unsigned salo = sbase + O_ALO;

    const int t = threadIdx.x;
    const int bx = blockIdx.x;
    const bool fw = bx < nb1;
    const float* W = fw ? W1 : W2;
    float* P = fw ? P1 : P2;
    const int nrows = fw ? n1 : n2;
    const int n0 = (fw ? bx : bx - nb1) * 128;

    // uneven k-split over 32-wide tiles
    const int TT = Kt >> 5;
    const int G = gridDim.y;
    const int base = TT / G;
    const int rem = TT - base * G;
    const int by = blockIdx.y;
    const int tBeg = by * base + (by < rem ? by : rem);
    const int NCH = base + (by < rem ? 1 : 0);
    const int kBeg = tBeg << 5;

    const int wid = t >> 5, l = t & 31;
    const int wm = (wid & 1) * 16;
    const int wn = (wid >> 1) * 32;

    const int lr = t >> 3;        // 0..31
    const int lc = t & 7;         // float4 col
    const float* wsrc = W + (size_t)(n0 + lr) * Kt + kBeg + lc * 4;
    const float* asrc = A + (size_t)lr * Kt + kBeg + lc * 4;
    const int wsl = lr * 32 + lc * 4;   // stage slot (per 32-row group)
    const int asl = lr * 32 + lc * 4;

    float acc[4][4];
    #pragma unroll
    for (int i = 0; i < 4; i++)
        #pragma unroll
        for (int j = 0; j < 4; j++) acc[i][j] = 0.f;

    // prologue: stage chunks 0,1
    {
        #pragma unroll
        for (int p = 0; p < 4; p++)
            cp16(&stW[p * 1024 + wsl], wsrc + (size_t)(p * 32) * Kt);
        cp16(&stA[asl], asrc);
        asm volatile("cp.async.commit_group;\n");
        if (NCH > 1) {
            #pragma unroll
            for (int p = 0; p < 4; p++)
                cp16(&stW[4096 + p * 1024 + wsl], wsrc + (size_t)(p * 32) * Kt + 32);
            cp16(&stA[1024 + asl], asrc + 32);
            asm volatile("cp.async.commit_group;\n");
        }
    }

    for (int ch = 0; ch < NCH; ch++) {
        const int st = ch & 1;
        if (ch + 1 < NCH) asm volatile("cp.async.wait_group 1;\n");
        else              asm volatile("cp.async.wait_group 0;\n");
        __syncthreads();   // stage ready + prev compute done reading bf16

        // convert fp32 stage -> bf16 hi/lo smem
        #pragma unroll
        for (int p = 0; p < 4; p++) {
            float4 v = *(const float4*)&stW[st * 4096 + p * 1024 + wsl];
            uint2 hi, lo; cvt_hilo(v, hi, lo);
            int bi = (lr + 32 * p) * SW + lc * 4;
            *(uint2*)&sWhi[bi] = hi;
            *(uint2*)&sWlo[bi] = lo;
        }
        {
            float4 v = *(const float4*)&stA[st * 1024 + asl];
            uint2 hi, lo; cvt_hilo(v, hi, lo);
            int bi = lr * SW + lc * 4;
            *(uint2*)&sAhi[bi] = hi;
            *(uint2*)&sAlo[bi] = lo;
        }
        __syncthreads();   // bf16 visible; stage reads complete

        // refill stage st with chunk ch+2
        if (ch + 2 < NCH) {
            #pragma unroll
            for (int p = 0; p < 4; p++)
                cp16(&stW[st * 4096 + p * 1024 + wsl],
                     wsrc + (size_t)(p * 32) * Kt + (ch + 2) * 32);
            cp16(&stA[st * 1024 + asl], asrc + (ch + 2) * 32);
            asm volatile("cp.async.commit_group;\n");
        }

        // compute: 2 k16 steps
        #pragma unroll
        for (int s = 0; s < 2; s++) {
            const int ks = s * 16;
            unsigned arow = wm + ((l >> 3) & 1) * 8 + (l & 7);
            unsigned acol = ks + ((l >> 4) & 1) * 8;
            unsigned aoff = (arow * SW + acol) * 2;
            unsigned ahi[4], alo[4];
            ldm4(ahi[0], ahi[1], ahi[2], ahi[3], sahi + aoff);
            ldm4(alo[0], alo[1], alo[2], alo[3], salo + aoff);
            unsigned brow = wn + ((l >> 4) & 1) * 8 + (l & 7);
            unsigned bcol = ks + ((l >> 3) & 1) * 8;
            unsigned boff0 = (brow * SW + bcol) * 2;
            unsigned boff1 = ((brow + 16) * SW + bcol) * 2;
            unsigned bhi[8], blo[8];
            ldm4(bhi[0], bhi[1], bhi[2], bhi[3], swhi + boff0);
            ldm4(bhi[4], bhi[5], bhi[6], bhi[7], swhi + boff1);
            ldm4(blo[0], blo[1], blo[2], blo[3], swlo + boff0);
            ldm4(blo[4], blo[5], blo[6], blo[7], swlo + boff1);
            #pragma unroll
            for (int tt = 0; tt < 4; tt++) {
                mma16816(acc[tt], ahi, bhi[tt*2], bhi[tt*2+1]);
                mma16816(acc[tt], ahi, blo[tt*2], blo[tt*2+1]);
                mma16816(acc[tt], alo, bhi[tt*2], bhi[tt*2+1]);
            }
        }
    }

    // ---- epilogue: partials [split][b][n] ----
    const int r0 = wm + (l >> 2);
    const int cb = n0 + wn + 2 * (l & 3);
    float* p0 = P + ((size_t)blockIdx.y * 32 + r0) * nrows;
    float* p1 = p0 + (size_t)8 * nrows;
    #pragma unroll
    for (int tt = 0; tt < 4; tt++) {
        *(float2*)(p0 + cb + tt * 8) = make_float2(acc[tt][0], acc[tt][1]);
        *(float2*)(p1 + cb + tt * 8) = make_float2(acc[tt][2], acc[tt][3]);
    }
}

// ============================================================================
// RMSNorm
// ============================================================================
__global__ void rmsnorm_kernel(const float* __restrict__ x,
                               const float* __restrict__ rms_w)
{
    __shared__ float red[256];
    int b = blockIdx.x;
    int tid = threadIdx.x;
    const float* xr = x + b * HID;
    float s = 0.f;
    for (int i = tid; i < HID; i += 256) { float v = xr[i]; s += v * v; }
    red[tid] = s; __syncthreads();
    for (int st = 128; st > 0; st >>= 1) {
        if (tid < st) red[tid] += red[tid + st];
        __syncthreads();
    }
    float rstd = rsqrtf(red[0] / (float)HID + EPS);
    float* o = g_xn + b * HID;
    for (int i = tid; i < HID; i += 256) o[i] = xr[i] * rstd * rms_w[i];
}

// ============================================================================
// Split-K reduce: C = sum_s part[s] (+ addv)
// ============================================================================
template<int S>
__global__ void reduce_split_t(const float* __restrict__ part, int elems,
                               const float* __restrict__ addv,
                               float* __restrict__ C)
{
    int i = blockIdx.x * blockDim.x + threadIdx.x;
    const float4* p = (const float4*)part;
    int q = elems >> 2;
    float4 s = p[i];
    #pragma unroll
    for (int j = 1; j < S; j++) {
        float4 t = p[i + (size_t)j * q];
        s.x += t.x; s.y += t.y; s.z += t.z; s.w += t.w;
    }
    if (addv) {
        float4 a = ((const float4*)addv)[i];
        s.x += a.x; s.y += a.y; s.z += a.z; s.w += a.w;
    }
    ((float4*)C)[i] = s;
}

// ============================================================================
// Conv + fused xm split-4 reduce + silu + new_conv_state  (4 channels/thread)
// ============================================================================
__global__ void conv_kernel(const float* __restrict__ conv_state,
                            const float* __restrict__ conv_w,
                            const float* __restrict__ conv_b,
                            const float* __restrict__ xm_part,
                            float* __restrict__ out)
{
    int i4 = blockIdx.x * blockDim.x + threadIdx.x;
    if (i4 >= BB * INNER / 4) return;
    int idx = i4 * 4;                 // b*INNER + c, multiple of 4
    int c = idx & (INNER - 1);

    float4 xm = make_float4(0.f, 0.f, 0.f, 0.f);
    #pragma unroll
    for (int s = 0; s < 4; s++) {
        float4 tpt = *(const float4*)(xm_part + (size_t)s * BB * INNER + idx);
        xm.x += tpt.x; xm.y += tpt.y; xm.z += tpt.z; xm.w += tpt.w;
    }

    const float4* cs = (const float4*)(conv_state + (size_t)idx * 3);
    float4 f0 = cs[0], f1 = cs[1], f2 = cs[2];
    const float4* w4 = (const float4*)(conv_w + c * 4);
    float4 w0 = w4[0], w1 = w4[1], w2 = w4[2], w3 = w4[3];
    float4 cb = *(const float4*)(conv_b + c);

    float xc0 = f0.x*w0.x + f0.y*w0.y + f0.z*w0.z + xm.x*w0.w + cb.x;
    float xc1 = f0.w*w1.x + f1.x*w1.y + f1.y*w1.z + xm.y*w1.w + cb.y;
    float xc2 = f1.z*w2.x + f1.w*w2.y + f2.x*w2.z + xm.z*w2.w + cb.z;
    float xc3 = f2.y*w3.x + f2.z*w3.y + f2.w*w3.z + xm.w*w3.w + cb.w;

    float4* nc = (float4*)(out + CONV_OFF + (size_t)idx * 3);
    nc[0] = make_float4(f0.y, f0.z, xm.x, f1.x);
    nc[1] = make_float4(f1.y, xm.y, f1.w, f2.x);
    nc[2] = make_float4(xm.z, f2.z, f2.w, xm.w);

    float4 o;
    o.x = xc0 / (1.f + expf(-xc0));
    o.y = xc1 / (1.f + expf(-xc1));
    o.z = xc2 / (1.f + expf(-xc2));
    o.w = xc3 / (1.f + expf(-xc3));
    *(float4*)&g_xmc[idx] = o;
}

// ============================================================================
// Gates
// ============================================================================
__global__ __launch_bounds__(256) void gate_kernel(
    const float* __restrict__ Wi, const float* __restrict__ bi,
    const float* __restrict__ Wf, const float* __restrict__ bf,
    const float* __restrict__ max_state,
    float* __restrict__ out)
{
    __shared__ float ri[256], rf[256];
    int bh = blockIdx.x;
    int h = bh & (NH - 1);
    int b = bh >> 3;
    int tid = threadIdx.x;
    const float4* q4  = (const float4*)(g_qkv + (size_t)b * K3);
    const float4* wi4 = (const float4*)(Wi + (size_t)h * K3);
    const float4* wf4 = (const float4*)(Wf + (size_t)h * K3);
    float si = 0.f, sf = 0.f;
    #pragma unroll
    for (int r = 0; r < K3/4/256; r++) {
        int j = tid + r * 256;
        float4 q = q4[j], a = wi4[j], f = wf4[j];
        si += q.x*a.x + q.y*a.y + q.z*a.z + q.w*a.w;
        sf += q.x*f.x + q.y*f.y + q.z*f.z + q.w*f.w;
    }
    ri[tid] = si; rf[tid] = sf; __syncthreads();
    for (int st = 128; st > 0; st >>= 1) {
        if (tid < st) { ri[tid] += ri[tid+st]; rf[tid] += rf[tid+st]; }
        __syncthreads();
    }
    if (tid == 0) {
        float ig = CAP * tanhf((ri[0] + bi[h]) / CAP);
        float fg = CAP * tanhf((rf[0] + bf[h]) / CAP);
        float lf = (fg >= 0.f) ? -log1pf(expf(-fg)) : (fg - log1pf(expf(fg)));
        float m_old = max_state[bh];
        float m_new = fmaxf(ig, m_old + lf);
        g_ig[bh] = expf(ig - m_new);
        g_fg[bh] = expf(lf + m_old - m_new);
        out[MAX_OFF + bh] = m_new;
    }
}

// ============================================================================
// Cell stream: grid = 4 chunks x 256 bh; 256 threads.
// ============================================================================
__global__ __launch_bounds__(256) void cell_stream(
    const float* __restrict__ cell_state,
    float* __restrict__ out)
{
    __shared__ float qsm[128], ksm[128];
    __shared__ float part[2][HEAD];

    const int bid = blockIdx.x;
    const int bh = bid >> 2;
    const int ch = bid & 3;
    const int h = bh & (NH - 1);
    const int b = bh >> 3;
    const int tid = threadIdx.x;

    const float* qrow = g_qkv + (size_t)b * K3 + h * HEAD;
    const float* krow = qrow + INNER;
    const float* vrow = qrow + 2 * INNER;
    const int d0 = ch * 128;

    if (tid < 128) {
        qsm[tid] = qrow[d0 + tid];
        ksm[tid] = krow[d0 + tid] * KSCALE;
    }
    __syncthreads();

    const float ig = g_ig[bh];
    const float fg = g_fg[bh];

    const int ct = tid & 127;
    const int rg = tid >> 7;
    const int e0 = ct * 4;
    float4 v = *(const float4*)(vrow + e0);
    float4 iv = make_float4(ig*v.x, ig*v.y, ig*v.z, ig*v.w);

    const float* cin  = cell_state + (size_t)bh * HEAD * HEAD;
    float*       cout = out + CELL_OFF + (size_t)bh * HEAD * HEAD;

    float4 nacc = make_float4(0.f, 0.f, 0.f, 0.f);
    #pragma unroll 8
    for (int dd = rg; dd < 128; dd += 2) {
        int d = d0 + dd;
        float4 cv = *(const float4*)(cin + (size_t)d * HEAD + e0);
        float kd = ksm[dd];
        float4 c;
        c.x = fmaf(fg, cv.x, kd * iv.x);
        c.y = fmaf(fg, cv.y, kd * iv.y);
        c.z = fmaf(fg, cv.z, kd * iv.z);
        c.w = fmaf(fg, cv.w, kd * iv.w);
        *(float4*)(cout + (size_t)d * HEAD + e0) = c;
        float qd = qsm[dd];
        nacc.x = fmaf(qd, c.x, nacc.x);
        nacc.y = fmaf(qd, c.y, nacc.y);
        nacc.z = fmaf(qd, c.z, nacc.z);
        nacc.w = fmaf(qd, c.w, nacc.w);
    }
    *(float4*)&part[rg][e0] = nacc;
    __syncthreads();
    if (tid < 128) {
        float4 p0 = *(const float4*)&part[0][e0];
        float4 p1 = *(const float4*)&part[1][e0];
        float4 s = make_float4(p0.x+p1.x, p0.y+p1.y, p0.z+p1.z, p0.w+p1.w);
        *(float4*)(g_numer + (size_t)bid * HEAD + e0) = s;
    }
}

// ============================================================================
// Cell epilogue: norm_new + qn + denom + GroupNorm + gating -> h
// (x_gate split-4 reduce fused)
// ============================================================================
__global__ __launch_bounds__(512) void cell_epi(
    const float* __restrict__ norm_state,
    const float* __restrict__ gn_w, const float* __restrict__ gn_b,
    const float* __restrict__ skip_w,
    const float* __restrict__ xg_part,
    float* __restrict__ out)
{
    __shared__ float red[512];
    const int bh = blockIdx.x;
    const int h = bh & (NH - 1);
    const int b = bh >> 3;
    const int tid = threadIdx.x;

    const float* qrow = g_qkv + (size_t)b * K3 + h * HEAD;
    const float* krow = qrow + INNER;
    float q = qrow[tid];
    float k = krow[tid] * KSCALE;

    const float ig = g_ig[bh];
    const float fg = g_fg[bh];
    const float m_new = out[MAX_OFF + bh];

    float num = g_numer[(size_t)(bh*4+0) * HEAD + tid]
              + g_numer[(size_t)(bh*4+1) * HEAD + tid]
              + g_numer[(size_t)(bh*4+2) * HEAD + tid]
              + g_numer[(size_t)(bh*4+3) * HEAD + tid];

    float nn = fmaf(fg, norm_state[(size_t)bh * HEAD + tid], ig * k);
    out[NORM_OFF + (size_t)bh * HEAD + tid] = nn;

    red[tid] = q * nn; __syncthreads();
    for (int st = 256; st > 0; st >>= 1) {
        if (tid < st) red[tid] += red[tid+st];
        __syncthreads();
    }
    float qn = red[0]; __syncthreads();
    float denom = fmaxf(fabsf(qn), expf(-m_new)) + EPS;
    float o = num / denom;

    red[tid] = o; __syncthreads();
    for (int st = 256; st > 0; st >>= 1) {
        if (tid < st) red[tid] += red[tid+st];
        __syncthreads();
    }
    float mu = red[0] / (float)HEAD; __syncthreads();
    float dv = o - mu;
    red[tid] = dv * dv; __syncthreads();
    for (int st = 256; st > 0; st >>= 1) {
        if (tid < st) red[tid] += red[tid+st];
        __syncthreads();
    }
    float rstd = rsqrtf(red[0] / (float)HEAD + GN_EPS);

    int c = h * HEAD + tid;
    size_t gidx = (size_t)b * INNER + c;
    float xg = 0.f;
    #pragma unroll
    for (int s = 0; s < 4; s++) xg += xg_part[(size_t)s * BB * INNER + gidx];
    float og = fmaf(dv * rstd, gn_w[c], gn_b[c]);
    float sg = xg / (1.f + expf(-xg));
    g_h[gidx] = (og + skip_w[c] * g_xmc[gidx]) * sg;
}

// ============================================================================
extern "C" void kernel_launch(void* const* d_in, const int* in_sizes, int n_in,
                              void* d_out, int out_size)
{
    const float* x          = (const float*)d_in[0];
    const float* conv_state = (const float*)d_in[1];
    const float* cell_state = (const float*)d_in[2];
    const float* norm_state = (const float*)d_in[3];
    const float* max_state  = (const float*)d_in[4];
    const float* rms_w      = (const float*)d_in[5];
    const float* Wx         = (const float*)d_in[6];
    const float* Wg         = (const float*)d_in[7];
    const float* Wqkv       = (const float*)d_in[8];
    const float* conv_w     = (const float*)d_in[9];
    const float* conv_b     = (const float*)d_in[10];
    const float* Wi         = (const float*)d_in[11];
    const float* bi         = (const float*)d_in[12];
    const float* Wf         = (const float*)d_in[13];
    const float* bf         = (const float*)d_in[14];
    const float* gn_w       = (const float*)d_in[15];
    const float* gn_b       = (const float*)d_in[16];
    const float* Wdown      = (const float*)d_in[17];
    const float* skip_w     = (const float*)d_in[18];
    float* out = (float*)d_out;

    float* pxn;   cudaGetSymbolAddress((void**)&pxn,   g_xn);
    float* pxmc;  cudaGetSymbolAddress((void**)&pxmc,  g_xmc);
    float* pqkv;  cudaGetSymbolAddress((void**)&pqkv,  g_qkv);
    float* ph;    cudaGetSymbolAddress((void**)&ph,    g_h);
    float* ppart; cudaGetSymbolAddress((void**)&ppart, g_part);

    // Wg partials: beyond QKV's split region (max 4*BB*K3)
    float* pp2 = ppart + (size_t)4 * BB * K3;

    cudaFuncSetAttribute(mma_gemm, cudaFuncAttributeMaxDynamicSharedMemorySize,
                         SMEM_MMA);

    // 1) rmsnorm
    rmsnorm_kernel<<<BB, 256>>>(x, rms_w);

    // 2) x_mlstm & x_gate tensor-core GEMM, split-K 4: grid (32+32, 4) = 256
    mma_gemm<<<dim3(64, 4), 256, SMEM_MMA>>>(pxn, Wx, ppart, INNER,
                                             Wg, pp2, INNER, 32, HID);

    // 3) conv (fused xm split-4 reduce) + silu + new_conv_state
    conv_kernel<<<(BB*INNER/4)/256, 256>>>(conv_state, conv_w, conv_b, ppart, out);

    // 4) qkv = xmc @ Wqkv^T, uneven split-K 3: grid (96, 3) = 288 (balanced 2/SM)
    mma_gemm<<<dim3(96, 3), 256, SMEM_MMA>>>(pxmc, Wqkv, ppart, K3,
                                             Wqkv, ppart, K3, 96, INNER);
    reduce_split_t<3><<<(BB*K3/4)/256, 256>>>(ppart, BB*K3, nullptr, pqkv);

    // 5) gates
    gate_kernel<<<BB*NH, 256>>>(Wi, bi, Wf, bf, max_state, out);

    // 6) cell stream: 1024 blocks
    cell_stream<<<BB*NH*4, 256>>>(cell_state, out);

    // 7) cell epilogue (fused xg reduce) -> h
    cell_epi<<<BB*NH, 512>>>(norm_state, gn_w, gn_b, skip_w, pp2, out);

    // 8) y = h @ Wdown^T + x, uneven split-K 24: grid (16, 24) = 384 (1 wave)
    mma_gemm<<<dim3(16, 24), 256, SMEM_MMA>>>(ph, Wdown, ppart, HID,
                                              Wdown, ppart, HID, 16, INNER);
    reduce_split_t<24><<<(BB*HID/4)/256, 256>>>(ppart, BB*HID, x, out + Y_OFF);
}

// round 17
// speedup vs baseline: 1.3253x; 1.0159x over previous
#include <cuda_runtime.h>
#include <cuda_bf16.h>
#include <math.h>
#include <stdint.h>

#define BB 32
#define HID 2048
#define INNER 4096
#define NH 8
#define HEAD 512
#define K3 12288
#define CAP 30.0f
#define EPS 1e-6f
#define GN_EPS 1e-5f
#define KSCALE 0.044194173824159216f   // 1/sqrt(512)

// ---------------- scratch (device globals; no allocs allowed) ----------------
__device__ float g_xn   [BB * HID];
__device__ float g_xg   [BB * INNER];
__device__ float g_xmc  [BB * INNER];
__device__ float g_qkv  [BB * K3];
__device__ float g_h    [BB * INNER];
__device__ float g_part [16 * BB * K3];            // split-K partials
__device__ float g_numer[BB * NH * 4 * HEAD];      // cell numer partials
__device__ float g_ig   [BB * NH];
__device__ float g_fg   [BB * NH];

// ---------------- output layout ----------------
#define Y_OFF    0
#define CONV_OFF 65536
#define CELL_OFF 458752
#define NORM_OFF 67567616
#define MAX_OFF  67698688

// ---------------- mma.sync helpers (sm_80 baseline PTX -> HMMA) -------------
__device__ __forceinline__ unsigned pack2(float c0, float c1) {
    unsigned r;
    asm("cvt.rn.satfinite.bf16x2.f32 %0, %1, %2;" : "=r"(r) : "f"(c1), "f"(c0));
    return r;
}

__device__ __forceinline__ void ldm4(unsigned& r0, unsigned& r1,
                                     unsigned& r2, unsigned& r3, unsigned addr) {
    asm volatile("ldmatrix.sync.aligned.m8n8.x4.shared.b16 {%0,%1,%2,%3}, [%4];"
                 : "=r"(r0), "=r"(r1), "=r"(r2), "=r"(r3) : "r"(addr));
}

__device__ __forceinline__ void mma16816(float* d, const unsigned* a,
                                         unsigned b0, unsigned b1) {
    asm volatile(
        "mma.sync.aligned.m16n8k16.row.col.f32.bf16.bf16.f32 "
        "{%0,%1,%2,%3}, {%4,%5,%6,%7}, {%8,%9}, {%0,%1,%2,%3};"
        : "+f"(d[0]), "+f"(d[1]), "+f"(d[2]), "+f"(d[3])
        : "r"(a[0]), "r"(a[1]), "r"(a[2]), "r"(a[3]), "r"(b0), "r"(b1));
}

__device__ __forceinline__ void cvt_hilo(float4 v, uint2& hi, uint2& lo) {
    unsigned hi01 = pack2(v.x, v.y);
    unsigned hi23 = pack2(v.z, v.w);
    float h0 = __uint_as_float(hi01 << 16);
    float h1 = __uint_as_float(hi01 & 0xFFFF0000u);
    float h2 = __uint_as_float(hi23 << 16);
    float h3 = __uint_as_float(hi23 & 0xFFFF0000u);
    hi = make_uint2(hi01, hi23);
    lo = make_uint2(pack2(v.x - h0, v.y - h1), pack2(v.z - h2, v.w - h3));
}

__device__ __forceinline__ void cp16(void* smem_p, const void* g) {
    unsigned s = (unsigned)__cvta_generic_to_shared(smem_p);
    asm volatile("cp.async.cg.shared.global [%0], [%1], 16;\n" :: "r"(s), "l"(g));
}

// ============================================================================
// MMA GEMM: C[32,N] = A[32,K] @ W[N,K]^T, bf16 hi/lo x3, uneven split-K.
// 256 thr, BN=128, BK=32. cp.async 2-deep fp32 staging for BOTH W and A
// -> convert -> bf16 smem -> mma.sync. Warp (of 8): 16m x 32n tile.
// Partial layout: [splitIdx][32][nrows]. Dual-W via nb1.
// ============================================================================
#define SW 40   // bf16 smem row stride (80B) - ldmatrix conflict-free
// dynamic smem offsets (bytes)
#define O_WST 0               // fp32 W stage: 2 * 128*32*4 = 32768
#define O_AST 32768           // fp32 A stage: 2 * 32*32*4  = 8192
#define O_WHI 40960           // 128*SW*2 = 10240
#define O_WLO 51200
#define O_AHI 61440           // 32*SW*2 = 2560
#define O_ALO 64000
#define SMEM_MMA 66560

__global__ __launch_bounds__(256) void mma_gemm(
    const float* __restrict__ A,
    const float* __restrict__ W1, float* __restrict__ P1, int n1,
    const float* __restrict__ W2, float* __restrict__ P2, int n2,
    int nb1, int Kt)
{
    extern __shared__ __align__(16) char smem[];
    float* stW = (float*)(smem + O_WST);
    float* stA = (float*)(smem + O_AST);
    __nv_bfloat16* sWhi = (__nv_bfloat16*)(smem + O_WHI);
    __nv_bfloat16* sWlo = (__nv_bfloat16*)(smem + O_WLO);
    __nv_bfloat16* sAhi = (__nv_bfloat16*)(smem + O_AHI);
    __nv_bfloat16* sAlo = (__nv_bfloat16*)(smem + O_ALO);
    const unsigned sbase = (unsigned)__cvta_generic_to_shared(smem);
    const unsigned swhi = sbase + O_WHI;
    const unsigned swlo = sbase + O_WLO;
    const unsigned sahi = sbase + O_AHI;
    const unsigned salo = sbase + O_ALO;

    const int t = threadIdx.x;
    const int bx = blockIdx.x;
    const bool fw = bx < nb1;
    const float* W = fw ? W1 : W2;
    float* P = fw ? P1 : P2;
    const int nrows = fw ? n1 : n2;
    const int n0 = (fw ? bx : bx - nb1) * 128;

    // uneven k-split over 32-wide tiles
    const int TT = Kt >> 5;
    const int G = gridDim.y;
    const int base = TT / G;
    const int rem = TT - base * G;
    const int by = blockIdx.y;
    const int tBeg = by * base + (by < rem ? by : rem);
    const int NCH = base + (by < rem ? 1 : 0);
    const int kBeg = tBeg << 5;

    const int wid = t >> 5, l = t & 31;
    const int wm = (wid & 1) * 16;
    const int wn = (wid >> 1) * 32;

    const int lr = t >> 3;        // 0..31
    const int lc = t & 7;         // float4 col
    const float* wsrc = W + (size_t)(n0 + lr) * Kt + kBeg + lc * 4;
    const float* asrc = A + (size_t)lr * Kt + kBeg + lc * 4;
    const int wsl = lr * 32 + lc * 4;   // stage slot (per 32-row group)
    const int asl = lr * 32 + lc * 4;

    float acc[4][4];
    #pragma unroll
    for (int i = 0; i < 4; i++)
        #pragma unroll
        for (int j = 0; j < 4; j++) acc[i][j] = 0.f;

    // prologue: stage chunks 0,1
    {
        #pragma unroll
        for (int p = 0; p < 4; p++)
            cp16(&stW[p * 1024 + wsl], wsrc + (size_t)(p * 32) * Kt);
        cp16(&stA[asl], asrc);
        asm volatile("cp.async.commit_group;\n");
        if (NCH > 1) {
            #pragma unroll
            for (int p = 0; p < 4; p++)
                cp16(&stW[4096 + p * 1024 + wsl], wsrc + (size_t)(p * 32) * Kt + 32);
            cp16(&stA[1024 + asl], asrc + 32);
            asm volatile("cp.async.commit_group;\n");
        }
    }

    for (int ch = 0; ch < NCH; ch++) {
        const int st = ch & 1;
        if (ch + 1 < NCH) asm volatile("cp.async.wait_group 1;\n");
        else              asm volatile("cp.async.wait_group 0;\n");
        __syncthreads();   // stage ready + prev compute done reading bf16

        // convert fp32 stage -> bf16 hi/lo smem
        #pragma unroll
        for (int p = 0; p < 4; p++) {
            float4 v = *(const float4*)&stW[st * 4096 + p * 1024 + wsl];
            uint2 hi, lo; cvt_hilo(v, hi, lo);
            int bi = (lr + 32 * p) * SW + lc * 4;
            *(uint2*)&sWhi[bi] = hi;
            *(uint2*)&sWlo[bi] = lo;
        }
        {
            float4 v = *(const float4*)&stA[st * 1024 + asl];
            uint2 hi, lo; cvt_hilo(v, hi, lo);
            int bi = lr * SW + lc * 4;
            *(uint2*)&sAhi[bi] = hi;
            *(uint2*)&sAlo[bi] = lo;
        }
        __syncthreads();   // bf16 visible; stage reads complete

        // refill stage st with chunk ch+2
        if (ch + 2 < NCH) {
            #pragma unroll
            for (int p = 0; p < 4; p++)
                cp16(&stW[st * 4096 + p * 1024 + wsl],
                     wsrc + (size_t)(p * 32) * Kt + (ch + 2) * 32);
            cp16(&stA[st * 1024 + asl], asrc + (ch + 2) * 32);
            asm volatile("cp.async.commit_group;\n");
        }

        // compute: 2 k16 steps
        #pragma unroll
        for (int s = 0; s < 2; s++) {
            const int ks = s * 16;
            unsigned arow = wm + ((l >> 3) & 1) * 8 + (l & 7);
            unsigned acol = ks + ((l >> 4) & 1) * 8;
            unsigned aoff = (arow * SW + acol) * 2;
            unsigned ahi[4], alo[4];
            ldm4(ahi[0], ahi[1], ahi[2], ahi[3], sahi + aoff);
            ldm4(alo[0], alo[1], alo[2], alo[3], salo + aoff);
            unsigned brow = wn + ((l >> 4) & 1) * 8 + (l & 7);
            unsigned bcol = ks + ((l >> 3) & 1) * 8;
            unsigned boff0 = (brow * SW + bcol) * 2;
            unsigned boff1 = ((brow + 16) * SW + bcol) * 2;
            unsigned bhi[8], blo[8];
            ldm4(bhi[0], bhi[1], bhi[2], bhi[3], swhi + boff0);
            ldm4(bhi[4], bhi[5], bhi[6], bhi[7], swhi + boff1);
            ldm4(blo[0], blo[1], blo[2], blo[3], swlo + boff0);
            ldm4(blo[4], blo[5], blo[6], blo[7], swlo + boff1);
            #pragma unroll
            for (int tt = 0; tt < 4; tt++) {
                mma16816(acc[tt], ahi, bhi[tt*2], bhi[tt*2+1]);
                mma16816(acc[tt], ahi, blo[tt*2], blo[tt*2+1]);
                mma16816(acc[tt], alo, bhi[tt*2], bhi[tt*2+1]);
            }
        }
    }

    // ---- epilogue: partials [split][b][n] ----
    const int r0 = wm + (l >> 2);
    const int cb = n0 + wn + 2 * (l & 3);
    float* p0 = P + ((size_t)blockIdx.y * 32 + r0) * nrows;
    float* p1 = p0 + (size_t)8 * nrows;
    #pragma unroll
    for (int tt = 0; tt < 4; tt++) {
        *(float2*)(p0 + cb + tt * 8) = make_float2(acc[tt][0], acc[tt][1]);
        *(float2*)(p1 + cb + tt * 8) = make_float2(acc[tt][2], acc[tt][3]);
    }
}

// ============================================================================
// RMSNorm
// ============================================================================
__global__ void rmsnorm_kernel(const float* __restrict__ x,
                               const float* __restrict__ rms_w)
{
    __shared__ float red[256];
    int b = blockIdx.x;
    int tid = threadIdx.x;
    const float* xr = x + b * HID;
    float s = 0.f;
    for (int i = tid; i < HID; i += 256) { float v = xr[i]; s += v * v; }
    red[tid] = s; __syncthreads();
    for (int st = 128; st > 0; st >>= 1) {
        if (tid < st) red[tid] += red[tid + st];
        __syncthreads();
    }
    float rstd = rsqrtf(red[0] / (float)HID + EPS);
    float* o = g_xn + b * HID;
    for (int i = tid; i < HID; i += 256) o[i] = xr[i] * rstd * rms_w[i];
}

// ============================================================================
// Split-K reduce: C = sum_s part[s] (+ addv)
// ============================================================================
template<int S>
__global__ void reduce_split_t(const float* __restrict__ part, int elems,
                               const float* __restrict__ addv,
                               float* __restrict__ C)
{
    int i = blockIdx.x * blockDim.x + threadIdx.x;
    const float4* p = (const float4*)part;
    int q = elems >> 2;
    float4 s = p[i];
    #pragma unroll
    for (int j = 1; j < S; j++) {
        float4 t = p[i + (size_t)j * q];
        s.x += t.x; s.y += t.y; s.z += t.z; s.w += t.w;
    }
    if (addv) {
        float4 a = ((const float4*)addv)[i];
        s.x += a.x; s.y += a.y; s.z += a.z; s.w += a.w;
    }
    ((float4*)C)[i] = s;
}

// ============================================================================
// Conv + fused xm split-4 reduce + silu + new_conv_state  (4 channels/thread)
// ============================================================================
__global__ void conv_kernel(const float* __restrict__ conv_state,
                            const float* __restrict__ conv_w,
                            const float* __restrict__ conv_b,
                            const float* __restrict__ xm_part,
                            float* __restrict__ out)
{
    int i4 = blockIdx.x * blockDim.x + threadIdx.x;
    if (i4 >= BB * INNER / 4) return;
    int idx = i4 * 4;
    int c = idx & (INNER - 1);

    float4 xm = make_float4(0.f, 0.f, 0.f, 0.f);
    #pragma unroll
    for (int s = 0; s < 4; s++) {
        float4 tpt = *(const float4*)(xm_part + (size_t)s * BB * INNER + idx);
        xm.x += tpt.x; xm.y += tpt.y; xm.z += tpt.z; xm.w += tpt.w;
    }

    const float4* cs = (const float4*)(conv_state + (size_t)idx * 3);
    float4 f0 = cs[0], f1 = cs[1], f2 = cs[2];
    const float4* w4 = (const float4*)(conv_w + c * 4);
    float4 w0 = w4[0], w1 = w4[1], w2 = w4[2], w3 = w4[3];
    float4 cb = *(const float4*)(conv_b + c);

    float xc0 = f0.x*w0.x + f0.y*w0.y + f0.z*w0.z + xm.x*w0.w + cb.x;
    float xc1 = f0.w*w1.x + f1.x*w1.y + f1.y*w1.z + xm.y*w1.w + cb.y;
    float xc2 = f1.z*w2.x + f1.w*w2.y + f2.x*w2.z + xm.z*w2.w + cb.z;
    float xc3 = f2.y*w3.x + f2.z*w3.y + f2.w*w3.z + xm.w*w3.w + cb.w;

    float4* nc = (float4*)(out + CONV_OFF + (size_t)idx * 3);
    nc[0] = make_float4(f0.y, f0.z, xm.x, f1.x);
    nc[1] = make_float4(f1.y, xm.y, f1.w, f2.x);
    nc[2] = make_float4(xm.z, f2.z, f2.w, xm.w);

    float4 o;
    o.x = xc0 / (1.f + expf(-xc0));
    o.y = xc1 / (1.f + expf(-xc1));
    o.z = xc2 / (1.f + expf(-xc2));
    o.w = xc3 / (1.f + expf(-xc3));
    *(float4*)&g_xmc[idx] = o;
}

// ============================================================================
// Gates + fused qkv split-3 reduce.
// Block (b,h): reduces partials on the fly for the gate dots, and writes the
// reduced q/k/v h-slices it owns ( ((j4>>7)&7)==h ) to g_qkv. 512 threads.
// ============================================================================
__global__ __launch_bounds__(512) void gate_kernel(
    const float* __restrict__ qkv_part,
    const float* __restrict__ Wi, const float* __restrict__ bi,
    const float* __restrict__ Wf, const float* __restrict__ bf,
    const float* __restrict__ max_state,
    float* __restrict__ out)
{
    __shared__ float ri[512], rf[512];
    int bh = blockIdx.x;
    int h = bh & (NH - 1);
    int b = bh >> 3;
    int tid = threadIdx.x;
    const float4* p0 = (const float4*)(qkv_part + (size_t)b * K3);
    const float4* p1 = (const float4*)(qkv_part + (size_t)(BB + b) * K3);
    const float4* p2 = (const float4*)(qkv_part + (size_t)(2 * BB + b) * K3);
    const float4* wi4 = (const float4*)(Wi + (size_t)h * K3);
    const float4* wf4 = (const float4*)(Wf + (size_t)h * K3);
    float4* qout = (float4*)(g_qkv + (size_t)b * K3);
    float si = 0.f, sf = 0.f;
    #pragma unroll
    for (int r = 0; r < K3/4/512; r++) {
        int j = tid + r * 512;
        float4 a = p0[j], bb = p1[j], cc = p2[j];
        float4 s = make_float4(a.x+bb.x+cc.x, a.y+bb.y+cc.y,
                               a.z+bb.z+cc.z, a.w+bb.w+cc.w);
        if (((j >> 7) & 7) == h) qout[j] = s;
        float4 wi = wi4[j], wf = wf4[j];
        si += s.x*wi.x + s.y*wi.y + s.z*wi.z + s.w*wi.w;
        sf += s.x*wf.x + s.y*wf.y + s.z*wf.z + s.w*wf.w;
    }
    ri[tid] = si; rf[tid] = sf; __syncthreads();
    for (int st = 256; st > 0; st >>= 1) {
        if (tid < st) { ri[tid] += ri[tid+st]; rf[tid] += rf[tid+st]; }
        __syncthreads();
    }
    if (tid == 0) {
        float ig = CAP * tanhf((ri[0] + bi[h]) / CAP);
        float fg = CAP * tanhf((rf[0] + bf[h]) / CAP);
        float lf = (fg >= 0.f) ? -log1pf(expf(-fg)) : (fg - log1pf(expf(fg)));
        float m_old = max_state[bh];
        float m_new = fmaxf(ig, m_old + lf);
        g_ig[bh] = expf(ig - m_new);
        g_fg[bh] = expf(lf + m_old - m_new);
        out[MAX_OFF + bh] = m_new;
    }
}

// ============================================================================
// Cell stream: grid = 4 chunks x 256 bh; 256 threads.
// ============================================================================
__global__ __launch_bounds__(256) void cell_stream(
    const float* __restrict__ cell_state,
    float* __restrict__ out)
{
    __shared__ float qsm[128], ksm[128];
    __shared__ float part[2][HEAD];

    const int bid = blockIdx.x;
    const int bh = bid >> 2;
    const int ch = bid & 3;
    const int h = bh & (NH - 1);
    const int b = bh >> 3;
    const int tid = threadIdx.x;

    const float* qrow = g_qkv + (size_t)b * K3 + h * HEAD;
    const float* krow = qrow + INNER;
    const float* vrow = qrow + 2 * INNER;
    const int d0 = ch * 128;

    if (tid < 128) {
        qsm[tid] = qrow[d0 + tid];
        ksm[tid] = krow[d0 + tid] * KSCALE;
    }
    __syncthreads();

    const float ig = g_ig[bh];
    const float fg = g_fg[bh];

    const int ct = tid & 127;
    const int rg = tid >> 7;
    const int e0 = ct * 4;
    float4 v = *(const float4*)(vrow + e0);
    float4 iv = make_float4(ig*v.x, ig*v.y, ig*v.z, ig*v.w);

    const float* cin  = cell_state + (size_t)bh * HEAD * HEAD;
    float*       cout = out + CELL_OFF + (size_t)bh * HEAD * HEAD;

    float4 nacc = make_float4(0.f, 0.f, 0.f, 0.f);
    #pragma unroll 8
    for (int dd = rg; dd < 128; dd += 2) {
        int d = d0 + dd;
        float4 cv = *(const float4*)(cin + (size_t)d * HEAD + e0);
        float kd = ksm[dd];
        float4 c;
        c.x = fmaf(fg, cv.x, kd * iv.x);
        c.y = fmaf(fg, cv.y, kd * iv.y);
        c.z = fmaf(fg, cv.z, kd * iv.z);
        c.w = fmaf(fg, cv.w, kd * iv.w);
        *(float4*)(cout + (size_t)d * HEAD + e0) = c;
        float qd = qsm[dd];
        nacc.x = fmaf(qd, c.x, nacc.x);
        nacc.y = fmaf(qd, c.y, nacc.y);
        nacc.z = fmaf(qd, c.z, nacc.z);
        nacc.w = fmaf(qd, c.w, nacc.w);
    }
    *(float4*)&part[rg][e0] = nacc;
    __syncthreads();
    if (tid < 128) {
        float4 p0 = *(const float4*)&part[0][e0];
        float4 p1 = *(const float4*)&part[1][e0];
        float4 s = make_float4(p0.x+p1.x, p0.y+p1.y, p0.z+p1.z, p0.w+p1.w);
        *(float4*)(g_numer + (size_t)bid * HEAD + e0) = s;
    }
}

// ============================================================================
// Cell epilogue: norm_new + qn + denom + GroupNorm + gating -> h
// (x_gate split-4 reduce fused)
// ============================================================================
__global__ __launch_bounds__(512) void cell_epi(
    const float* __restrict__ norm_state,
    const float* __restrict__ gn_w, const float* __restrict__ gn_b,
    const float* __restrict__ skip_w,
    const float* __restrict__ xg_part,
    float* __restrict__ out)
{
    __shared__ float red[512];
    const int bh = blockIdx.x;
    const int h = bh & (NH - 1);
    const int b = bh >> 3;
    const int tid = threadIdx.x;

    const float* qrow = g_qkv + (size_t)b * K3 + h * HEAD;
    const float* krow = qrow + INNER;
    float q = qrow[tid];
    float k = krow[tid] * KSCALE;

    const float ig = g_ig[bh];
    const float fg = g_fg[bh];
    const float m_new = out[MAX_OFF + bh];

    float num = g_numer[(size_t)(bh*4+0) * HEAD + tid]
              + g_numer[(size_t)(bh*4+1) * HEAD + tid]
              + g_numer[(size_t)(bh*4+2) * HEAD + tid]
              + g_numer[(size_t)(bh*4+3) * HEAD + tid];

    float nn = fmaf(fg, norm_state[(size_t)bh * HEAD + tid], ig * k);
    out[NORM_OFF + (size_t)bh * HEAD + tid] = nn;

    red[tid] = q * nn; __syncthreads();
    for (int st = 256; st > 0; st >>= 1) {
        if (tid < st) red[tid] += red[tid+st];
        __syncthreads();
    }
    float qn = red[0]; __syncthreads();
    float denom = fmaxf(fabsf(qn), expf(-m_new)) + EPS;
    float o = num / denom;

    red[tid] = o; __syncthreads();
    for (int st = 256; st > 0; st >>= 1) {
        if (tid < st) red[tid] += red[tid+st];
        __syncthreads();
    }
    float mu = red[0] / (float)HEAD; __syncthreads();
    float dv = o - mu;
    red[tid] = dv * dv; __syncthreads();
    for (int st = 256; st > 0; st >>= 1) {
        if (tid < st) red[tid] += red[tid+st];
        __syncthreads();
    }
    float rstd = rsqrtf(red[0] / (float)HEAD + GN_EPS);

    int c = h * HEAD + tid;
    size_t gidx = (size_t)b * INNER + c;
    float xg = 0.f;
    #pragma unroll
    for (int s = 0; s < 4; s++) xg += xg_part[(size_t)s * BB * INNER + gidx];
    float og = fmaf(dv * rstd, gn_w[c], gn_b[c]);
    float sg = xg / (1.f + expf(-xg));
    g_h[gidx] = (og + skip_w[c] * g_xmc[gidx]) * sg;
}

// ============================================================================
extern "C" void kernel_launch(void* const* d_in, const int* in_sizes, int n_in,
                              void* d_out, int out_size)
{
    const float* x          = (const float*)d_in[0];
    const float* conv_state = (const float*)d_in[1];
    const float* cell_state = (const float*)d_in[2];
    const float* norm_state = (const float*)d_in[3];
    const float* max_state  = (const float*)d_in[4];
    const float* rms_w      = (const float*)d_in[5];
    const float* Wx         = (const float*)d_in[6];
    const float* Wg         = (const float*)d_in[7];
    const float* Wqkv       = (const float*)d_in[8];
    const float* conv_w     = (const float*)d_in[9];
    const float* conv_b     = (const float*)d_in[10];
    const float* Wi         = (const float*)d_in[11];
    const float* bi         = (const float*)d_in[12];
    const float* Wf         = (const float*)d_in[13];
    const float* bf         = (const float*)d_in[14];
    const float* gn_w       = (const float*)d_in[15];
    const float* gn_b       = (const float*)d_in[16];
    const float* Wdown      = (const float*)d_in[17];
    const float* skip_w     = (const float*)d_in[18];
    float* out = (float*)d_out;

    float* pxn;   cudaGetSymbolAddress((void**)&pxn,   g_xn);
    float* pxmc;  cudaGetSymbolAddress((void**)&pxmc,  g_xmc);
    float* ph;    cudaGetSymbolAddress((void**)&ph,    g_h);
    float* ppart; cudaGetSymbolAddress((void**)&ppart, g_part);

    // Wg partials: beyond QKV's split region (max 4*BB*K3)
    float* pp2 = ppart + (size_t)4 * BB * K3;

    cudaFuncSetAttribute(mma_gemm, cudaFuncAttributeMaxDynamicSharedMemorySize,
                         SMEM_MMA);

    // 1) rmsnorm
    rmsnorm_kernel<<<BB, 256>>>(x, rms_w);

    // 2) x_mlstm & x_gate tensor-core GEMM, split-K 4: grid (32+32, 4) = 256
    mma_gemm<<<dim3(64, 4), 256, SMEM_MMA>>>(pxn, Wx, ppart, INNER,
                                             Wg, pp2, INNER, 32, HID);

    // 3) conv (fused xm split-4 reduce) + silu + new_conv_state
    conv_kernel<<<(BB*INNER/4)/256, 256>>>(conv_state, conv_w, conv_b, ppart, out);

    // 4) qkv = xmc @ Wqkv^T, uneven split-K 3: grid (96, 3) = 288
    mma_gemm<<<dim3(96, 3), 256, SMEM_MMA>>>(pxmc, Wqkv, ppart, K3,
                                             Wqkv, ppart, K3, 96, INNER);

    // 5) gates + fused qkv reduce (writes g_qkv)
    gate_kernel<<<BB*NH, 512>>>(ppart, Wi, bi, Wf, bf, max_state, out);

    // 6) cell stream: 1024 blocks
    cell_stream<<<BB*NH*4, 256>>>(cell_state, out);

    // 7) cell epilogue (fused xg reduce) -> h
    cell_epi<<<BB*NH, 512>>>(norm_state, gn_w, gn_b, skip_w, pp2, out);

    // 8) y = h @ Wdown^T + x, uneven split-K 24: grid (16, 24) = 384 (1 wave)
    mma_gemm<<<dim3(16, 24), 256, SMEM_MMA>>>(ph, Wdown, ppart, HID,
                                              Wdown, ppart, HID, 16, INNER);
    reduce_split_t<24><<<(BB*HID/4)/256, 256>>>(ppart, BB*HID, x, out + Y_OFF);
}